// round 10
// baseline (speedup 1.0000x reference)
#include <cuda_runtime.h>
#include <cuda_bf16.h>
#include <math.h>
#include <stdint.h>

// Problem constants
#define BB 2
#define TT 2048
#define DD 2048
#define HH 16
#define DKq 64
#define DVv 128
#define RR 16
#define CC 64
#define NCC 32
#define MM (BB*TT)          // 4096
#define NQK (HH*DKq)        // 1024
#define NV  (HH*DVv)        // 2048
#define GLN_INV (1.0f/16.0f)
#define EPSL 1e-5f

// ---------------- scratch (device globals, no allocs allowed) ----------------
__device__ float g_q [MM*NQK];
__device__ float g_k [MM*NQK];
__device__ float g_v [MM*NV];
__device__ float g_gk[MM*NQK];
__device__ float g_r1[MM*RR];
__device__ float g_r2[MM*RR];
__device__ float g_g [MM*NV];
__device__ float g_o [MM*NV];
__device__ float g_hsr[MM*DD];     // tf32-rounded + permuted hs
__device__ float g_wqr[DD*NQK];    // transposed [N][K] + permuted + rounded
__device__ float g_wkr[DD*NQK];
__device__ float g_wvr[DD*NV];
__device__ float g_wor[NV*DD];

// ---------------- helpers ----------------
__device__ __forceinline__ float f2tf32(float x) {
    uint32_t r;
    asm("cvt.rna.tf32.f32 %0, %1;" : "=r"(r) : "f"(x));
    return __uint_as_float(r);
}

__device__ __forceinline__ void cp16(void* smem_dst, const void* gmem_src) {
    uint32_t s = (uint32_t)__cvta_generic_to_shared(smem_dst);
    asm volatile("cp.async.cg.shared.global [%0], [%1], 16;" :: "r"(s), "l"(gmem_src));
}

// permutation within each 32-float K block: p(c) = (c&3)*8 + (c>>2)
// inverse: c(p) = (p&7)*4 + (p>>3)

// round hs to tf32 + permute
__global__ __launch_bounds__(256) void round_perm_kernel(
    const float* __restrict__ src, float* __restrict__ dst, int n4, int Kdim)
{
    int idx = blockIdx.x * 256 + threadIdx.x;
    if (idx >= n4) return;
    int q4 = Kdim >> 2;
    int m = idx / q4;
    int q = idx - m * q4;
    int kb = q >> 3;
    int j  = q & 7;
    const float* s = src + (long)m * Kdim + kb * 32;
    float4 o;
    int p0 = 4 * j;
    o.x = f2tf32(s[((p0    ) & 7) * 4 + ((p0    ) >> 3)]);
    o.y = f2tf32(s[((p0 + 1) & 7) * 4 + ((p0 + 1) >> 3)]);
    o.z = f2tf32(s[((p0 + 2) & 7) * 4 + ((p0 + 2) >> 3)]);
    o.w = f2tf32(s[((p0 + 3) & 7) * 4 + ((p0 + 3) >> 3)]);
    *(float4*)(dst + (long)m * Kdim + kb * 32 + p0) = o;
}

// merged transpose + round + permute for all 4 weights (z selects matrix)
__global__ __launch_bounds__(256) void transpose_perm_all_kernel(
    const float* __restrict__ Wq, const float* __restrict__ Wk,
    const float* __restrict__ Wv, const float* __restrict__ Wo,
    float* __restrict__ WTq, float* __restrict__ WTk,
    float* __restrict__ WTv, float* __restrict__ WTo)
{
    const float* W; float* WT; int K, N;
    switch (blockIdx.z) {
        case 0: W = Wq; WT = WTq; K = DD; N = NQK; break;
        case 1: W = Wk; WT = WTk; K = DD; N = NQK; break;
        case 2: W = Wv; WT = WTv; K = DD; N = NV;  break;
        default:W = Wo; WT = WTo; K = NV; N = DD;  break;
    }
    const int n0 = blockIdx.x * 32;
    const int k0 = blockIdx.y * 32;
    if (n0 >= N || k0 >= K) return;

    __shared__ float t[32][33];
    const int tx = threadIdx.x;       // 0..31
    const int ty = threadIdx.y;       // 0..7
#pragma unroll
    for (int i = 0; i < 4; i++)
        t[ty + 8*i][tx] = W[(long)(k0 + ty + 8*i) * N + n0 + tx];
    __syncthreads();
    int p0 = 4 * ty;
    float4 o;
    o.x = f2tf32(t[((p0    ) & 7) * 4 + ((p0    ) >> 3)][tx]);
    o.y = f2tf32(t[((p0 + 1) & 7) * 4 + ((p0 + 1) >> 3)][tx]);
    o.z = f2tf32(t[((p0 + 2) & 7) * 4 + ((p0 + 2) >> 3)][tx]);
    o.w = f2tf32(t[((p0 + 3) & 7) * 4 + ((p0 + 3) >> 3)][tx]);
    *(float4*)(WT + (long)(n0 + tx) * K + k0 + p0) = o;
}

// ---------------- merged q/k/v tf32 GEMM, BM=128 BN=128 ----------------
// grid (32, 32): blockIdx.x = virtual n-tile over [q|k|v] concat (4096 cols).
// 512 threads, 16 warps as 4(M)x4(N), warp tile 32x32, 3-stage cp.async.
#define QSTAGE_FLOATS (2*128*32)              // 8192 (A + B)
#define QSM_BYTES (3*QSTAGE_FLOATS*4)         // 98304

__global__ __launch_bounds__(512, 1) void tf32gemm_qkv_kernel(
    const float* __restrict__ A,
    const float* __restrict__ BTq, const float* __restrict__ BTk,
    const float* __restrict__ BTv,
    float* __restrict__ Cq, float* __restrict__ Ck, float* __restrict__ Cv)
{
    extern __shared__ float sm[];
    const int tid  = threadIdx.x;
    const int warp = tid >> 5;
    const int lane = tid & 31;
    const int g    = lane >> 2;          // 0..7
    const int tig  = lane & 3;           // 0..3
    const int wm   = (warp >> 2) * 32;   // 0,32,64,96
    const int wn   = (warp & 3) * 32;    // 0,32,64,96
    const int bm   = blockIdx.y * 128;
    const int K    = DD;
    const int NIT  = K >> 5;             // 64

    const int ntile = blockIdx.x;        // 0..31
    const float* BT; float* C; int Nloc; int bn;
    if (ntile < 8)       { BT = BTq; C = Cq; Nloc = NQK; bn = ntile * 128; }
    else if (ntile < 16) { BT = BTk; C = Ck; Nloc = NQK; bn = (ntile - 8) * 128; }
    else                 { BT = BTv; C = Cv; Nloc = NV;  bn = (ntile - 16) * 128; }

    float c[2][4][4];
#pragma unroll
    for (int mt = 0; mt < 2; mt++)
#pragma unroll
        for (int nt = 0; nt < 4; nt++)
#pragma unroll
            for (int r = 0; r < 4; r++) c[mt][nt][r] = 0.f;

    auto fill = [&](int t) {
        char* As = (char*)(sm + (t % 3) * QSTAGE_FLOATS);
        char* Bs = As + 128 * 128;       // A = 128 rows x 128 B
        const int kbase = t << 5;
        // A: 1024 chunks, 2/thread
#pragma unroll
        for (int i = 0; i < 2; i++) {
            int idx = tid + i * 512;
            int row = idx >> 3;
            int j   = idx & 7;
            cp16(As + row * 128 + ((j ^ (row & 7)) << 4),
                 A + (long)(bm + row) * K + kbase + j * 4);
        }
        // B: 1024 chunks, 2/thread
#pragma unroll
        for (int i = 0; i < 2; i++) {
            int idx = tid + i * 512;
            int row = idx >> 3;
            int j   = idx & 7;
            cp16(Bs + row * 128 + ((j ^ (row & 7)) << 4),
                 BT + (long)(bn + row) * K + kbase + j * 4);
        }
        asm volatile("cp.async.commit_group;");
    };

    fill(0); fill(1); fill(2);

    for (int t = 0; t < NIT; t++) {
        int rem = NIT - 1 - t;
        if (rem >= 2)      asm volatile("cp.async.wait_group 2;");
        else if (rem == 1) asm volatile("cp.async.wait_group 1;");
        else               asm volatile("cp.async.wait_group 0;");
        __syncthreads();

        const char* Ab = (const char*)(sm + (t % 3) * QSTAGE_FLOATS);
        const char* Bb = Ab + 128 * 128;

#pragma unroll
        for (int h = 0; h < 2; h++) {
            const int ch = ((2 * tig + h) ^ g) << 4;
            float4 av[2][2];
#pragma unroll
            for (int mt = 0; mt < 2; mt++) {
                int r1 = wm + mt * 16 + g;
                av[mt][0] = *(const float4*)(Ab + r1 * 128 + ch);
                av[mt][1] = *(const float4*)(Ab + (r1 + 8) * 128 + ch);
            }
            float4 bv[4];
#pragma unroll
            for (int nt = 0; nt < 4; nt++) {
                int rn = wn + nt * 8 + g;
                bv[nt] = *(const float4*)(Bb + rn * 128 + ch);
            }
#pragma unroll
            for (int nt = 0; nt < 4; nt++)
#pragma unroll
                for (int mt = 0; mt < 2; mt++) {
                    asm volatile(
                        "mma.sync.aligned.m16n8k8.row.col.f32.tf32.tf32.f32 "
                        "{%0,%1,%2,%3}, {%4,%5,%6,%7}, {%8,%9}, {%0,%1,%2,%3};"
                        : "+f"(c[mt][nt][0]), "+f"(c[mt][nt][1]),
                          "+f"(c[mt][nt][2]), "+f"(c[mt][nt][3])
                        : "r"(__float_as_uint(av[mt][0].x)), "r"(__float_as_uint(av[mt][1].x)),
                          "r"(__float_as_uint(av[mt][0].y)), "r"(__float_as_uint(av[mt][1].y)),
                          "r"(__float_as_uint(bv[nt].x)), "r"(__float_as_uint(bv[nt].y)));
                    asm volatile(
                        "mma.sync.aligned.m16n8k8.row.col.f32.tf32.tf32.f32 "
                        "{%0,%1,%2,%3}, {%4,%5,%6,%7}, {%8,%9}, {%0,%1,%2,%3};"
                        : "+f"(c[mt][nt][0]), "+f"(c[mt][nt][1]),
                          "+f"(c[mt][nt][2]), "+f"(c[mt][nt][3])
                        : "r"(__float_as_uint(av[mt][0].z)), "r"(__float_as_uint(av[mt][1].z)),
                          "r"(__float_as_uint(av[mt][0].w)), "r"(__float_as_uint(av[mt][1].w)),
                          "r"(__float_as_uint(bv[nt].z)), "r"(__float_as_uint(bv[nt].w)));
                }
        }
        __syncthreads();
        if (t + 3 < NIT) fill(t + 3);
    }

    // epilogue with silu
#pragma unroll
    for (int mt = 0; mt < 2; mt++) {
        int r0 = bm + wm + mt * 16 + g;
#pragma unroll
        for (int nt = 0; nt < 4; nt++) {
            int col = bn + wn + nt * 8 + tig * 2;
            float x0 = c[mt][nt][0], x1 = c[mt][nt][1];
            float x2 = c[mt][nt][2], x3 = c[mt][nt][3];
            x0 = x0 / (1.f + __expf(-x0));
            x1 = x1 / (1.f + __expf(-x1));
            x2 = x2 / (1.f + __expf(-x2));
            x3 = x3 / (1.f + __expf(-x3));
            *(float2*)(C + (long)r0 * Nloc + col)       = make_float2(x0, x1);
            *(float2*)(C + (long)(r0 + 8) * Nloc + col) = make_float2(x2, x3);
        }
    }
}

// ---------------- tf32 GEMM v4 (BN=256) for the output projection ------------
#define PSTAGE_A (128*32)
#define PSTAGE_B (256*32)
#define PSTAGE_FLOATS (PSTAGE_A + PSTAGE_B)   // 12288
#define PSM_BYTES (3*PSTAGE_FLOATS*4)         // 147456

__global__ __launch_bounds__(512, 1) void tf32gemm4_kernel(
    const float* __restrict__ A, const float* __restrict__ BT,
    float* __restrict__ C, int M, int N, int K)
{
    extern __shared__ float sm[];
    const int tid  = threadIdx.x;
    const int warp = tid >> 5;
    const int lane = tid & 31;
    const int g    = lane >> 2;
    const int tig  = lane & 3;
    const int wm   = (warp >> 2) * 32;
    const int wn   = (warp & 3) * 64;
    const int bm   = blockIdx.y * 128;
    const int bn   = blockIdx.x * 256;
    const int NIT  = K >> 5;

    float c[2][8][4];
#pragma unroll
    for (int mt = 0; mt < 2; mt++)
#pragma unroll
        for (int nt = 0; nt < 8; nt++)
#pragma unroll
            for (int r = 0; r < 4; r++) c[mt][nt][r] = 0.f;

    auto fill = [&](int t) {
        char* As = (char*)(sm + (t % 3) * PSTAGE_FLOATS);
        char* Bs = As + PSTAGE_A * 4;
        const int kbase = t << 5;
#pragma unroll
        for (int i = 0; i < 2; i++) {
            int idx = tid + i * 512;
            int row = idx >> 3;
            int j   = idx & 7;
            cp16(As + row * 128 + ((j ^ (row & 7)) << 4),
                 A + (long)(bm + row) * K + kbase + j * 4);
        }
#pragma unroll
        for (int i = 0; i < 4; i++) {
            int idx = tid + i * 512;
            int row = idx >> 3;
            int j   = idx & 7;
            cp16(Bs + row * 128 + ((j ^ (row & 7)) << 4),
                 BT + (long)(bn + row) * K + kbase + j * 4);
        }
        asm volatile("cp.async.commit_group;");
    };

    fill(0); fill(1); fill(2);

    for (int t = 0; t < NIT; t++) {
        int rem = NIT - 1 - t;
        if (rem >= 2)      asm volatile("cp.async.wait_group 2;");
        else if (rem == 1) asm volatile("cp.async.wait_group 1;");
        else               asm volatile("cp.async.wait_group 0;");
        __syncthreads();

        const char* Ab = (const char*)(sm + (t % 3) * PSTAGE_FLOATS);
        const char* Bb = Ab + PSTAGE_A * 4;

#pragma unroll
        for (int h = 0; h < 2; h++) {
            const int ch = ((2 * tig + h) ^ g) << 4;
            float4 av[2][2];
#pragma unroll
            for (int mt = 0; mt < 2; mt++) {
                int r1 = wm + mt * 16 + g;
                av[mt][0] = *(const float4*)(Ab + r1 * 128 + ch);
                av[mt][1] = *(const float4*)(Ab + (r1 + 8) * 128 + ch);
            }
#pragma unroll
            for (int ntp = 0; ntp < 4; ntp++) {
                float4 bv[2];
#pragma unroll
                for (int u = 0; u < 2; u++) {
                    int rn = wn + (ntp * 2 + u) * 8 + g;
                    bv[u] = *(const float4*)(Bb + rn * 128 + ch);
                }
#pragma unroll
                for (int u = 0; u < 2; u++) {
                    int nt = ntp * 2 + u;
#pragma unroll
                    for (int mt = 0; mt < 2; mt++) {
                        asm volatile(
                            "mma.sync.aligned.m16n8k8.row.col.f32.tf32.tf32.f32 "
                            "{%0,%1,%2,%3}, {%4,%5,%6,%7}, {%8,%9}, {%0,%1,%2,%3};"
                            : "+f"(c[mt][nt][0]), "+f"(c[mt][nt][1]),
                              "+f"(c[mt][nt][2]), "+f"(c[mt][nt][3])
                            : "r"(__float_as_uint(av[mt][0].x)), "r"(__float_as_uint(av[mt][1].x)),
                              "r"(__float_as_uint(av[mt][0].y)), "r"(__float_as_uint(av[mt][1].y)),
                              "r"(__float_as_uint(bv[u].x)), "r"(__float_as_uint(bv[u].y)));
                        asm volatile(
                            "mma.sync.aligned.m16n8k8.row.col.f32.tf32.tf32.f32 "
                            "{%0,%1,%2,%3}, {%4,%5,%6,%7}, {%8,%9}, {%0,%1,%2,%3};"
                            : "+f"(c[mt][nt][0]), "+f"(c[mt][nt][1]),
                              "+f"(c[mt][nt][2]), "+f"(c[mt][nt][3])
                            : "r"(__float_as_uint(av[mt][0].z)), "r"(__float_as_uint(av[mt][1].z)),
                              "r"(__float_as_uint(av[mt][0].w)), "r"(__float_as_uint(av[mt][1].w)),
                              "r"(__float_as_uint(bv[u].z)), "r"(__float_as_uint(bv[u].w)));
                    }
                }
            }
        }
        __syncthreads();
        if (t + 3 < NIT) fill(t + 3);
    }

#pragma unroll
    for (int mt = 0; mt < 2; mt++) {
        int r0 = bm + wm + mt * 16 + g;
#pragma unroll
        for (int nt = 0; nt < 8; nt++) {
            int col = bn + wn + nt * 8 + tig * 2;
            *(float2*)(C + (long)r0 * N + col)       = make_float2(c[mt][nt][0], c[mt][nt][1]);
            *(float2*)(C + (long)(r0 + 8) * N + col) = make_float2(c[mt][nt][2], c[mt][nt][3]);
        }
    }
}

// ---------------- fused low-rank stage 1: both gates, hs read once ----------
__global__ __launch_bounds__(256) void lowrank1_fused_kernel(
    const float* __restrict__ A, const float* __restrict__ W1,
    const float* __restrict__ W2, float* __restrict__ R1,
    float* __restrict__ R2, int K)
{
    const int warp = threadIdx.x >> 5;
    const int lane = threadIdx.x & 31;
    const int m = blockIdx.x * 8 + warp;
    const float* ap = A + (long)m * K;

    float acc1[16], acc2[16];
#pragma unroll
    for (int n = 0; n < 16; n++) { acc1[n] = 0.f; acc2[n] = 0.f; }

    for (int k = lane; k < K; k += 32) {
        float a = ap[k];
        const float4* w1 = (const float4*)(W1 + (long)k * 16);
        const float4* w2 = (const float4*)(W2 + (long)k * 16);
#pragma unroll
        for (int q = 0; q < 4; q++) {
            float4 u = w1[q];
            acc1[q*4+0] += a * u.x; acc1[q*4+1] += a * u.y;
            acc1[q*4+2] += a * u.z; acc1[q*4+3] += a * u.w;
            float4 v = w2[q];
            acc2[q*4+0] += a * v.x; acc2[q*4+1] += a * v.y;
            acc2[q*4+2] += a * v.z; acc2[q*4+3] += a * v.w;
        }
    }
#pragma unroll
    for (int n = 0; n < 16; n++) {
        float v = acc1[n];
        v += __shfl_xor_sync(0xffffffffu, v, 16);
        v += __shfl_xor_sync(0xffffffffu, v, 8);
        v += __shfl_xor_sync(0xffffffffu, v, 4);
        v += __shfl_xor_sync(0xffffffffu, v, 2);
        v += __shfl_xor_sync(0xffffffffu, v, 1);
        if (lane == 0) R1[(long)m * 16 + n] = v;
        float w = acc2[n];
        w += __shfl_xor_sync(0xffffffffu, w, 16);
        w += __shfl_xor_sync(0xffffffffu, w, 8);
        w += __shfl_xor_sync(0xffffffffu, w, 4);
        w += __shfl_xor_sync(0xffffffffu, w, 2);
        w += __shfl_xor_sync(0xffffffffu, w, 1);
        if (lane == 0) R2[(long)m * 16 + n] = w;
    }
}

// ---------------- low-rank stage 2 ----------------
__global__ __launch_bounds__(256) void lowrank2_kernel(
    const float* __restrict__ Rt, const float* __restrict__ W2,
    const float* __restrict__ bias, float* __restrict__ Out,
    int NOUT, int mode)
{
    int idx = blockIdx.x * 256 + threadIdx.x;
    int m = idx / NOUT;
    int n = idx - m * NOUT;
    const float* r = Rt + (long)m * 16;
    float acc = bias[n];
#pragma unroll
    for (int j = 0; j < 16; j++) acc += r[j] * W2[(long)j * NOUT + n];
    if (mode) {
        float x = acc;
        float ls = (x >= 0.f) ? -log1pf(__expf(-x)) : (x - log1pf(__expf(x)));
        acc = ls * GLN_INV;
    }
    Out[idx] = acc;
}

// ---------------- GLA chunked recurrence (512 threads) ----------------
#define OFF_Q  0
#define OFF_K  4160
#define OFF_A  8320
#define OFF_V  12480
#define OFF_S  14592
#define OFF_GL 16704
#define SM_FLOATS 16768
#define SM_BYTES  (SM_FLOATS * 4)

__global__ __launch_bounds__(512) void gla_kernel(
    const float* __restrict__ Q, const float* __restrict__ Kx,
    const float* __restrict__ V, const float* __restrict__ GK,
    float* __restrict__ O)
{
    extern __shared__ float sm[];
    float* sq  = sm + OFF_Q;
    float* sk  = sm + OFF_K;
    float* sA  = sm + OFF_A;
    float* sv  = sm + OFF_V;
    float* sS  = sm + OFF_S;
    float* sGl = sm + OFF_GL;

    const int tid = threadIdx.x;
    const int s  = blockIdx.x & 3;
    const int bh = blockIdx.x >> 2;
    const int h  = bh & 15;
    const int b  = bh >> 4;
    const int e0 = s * 32;

    const int cb = tid & 63;
    const int eg = tid >> 6;

    for (int i = tid; i < 64 * 33; i += 512) sS[i] = 0.f;

    for (int ch = 0; ch < NCC; ch++) {
        __syncthreads();
        const long base = ((long)(b * TT + ch * 64) * HH + h);
        const float* qp  = Q  + base * DKq;
        const float* kp  = Kx + base * DKq;
        const float* gp  = GK + base * DKq;
        const float* vp  = V  + base * DVv + e0;

#pragma unroll
        for (int w = 0; w < 2; w++) {
            int f = w * 512 + tid;
            int c = f >> 4;
            int dq = (f & 15) << 2;
            float4 a4 = *(const float4*)(qp + (long)c * 1024 + dq);
            sq[c*65+dq]=a4.x; sq[c*65+dq+1]=a4.y; sq[c*65+dq+2]=a4.z; sq[c*65+dq+3]=a4.w;
            float4 b4 = *(const float4*)(kp + (long)c * 1024 + dq);
            sk[c*65+dq]=b4.x; sk[c*65+dq+1]=b4.y; sk[c*65+dq+2]=b4.z; sk[c*65+dq+3]=b4.w;
            float4 g4 = *(const float4*)(gp + (long)c * 1024 + dq);
            sA[c*65+dq]=g4.x; sA[c*65+dq+1]=g4.y; sA[c*65+dq+2]=g4.z; sA[c*65+dq+3]=g4.w;
        }
        {
            int f = tid;
            int c = f >> 3;
            int eq = (f & 7) << 2;
            float4 v4 = *(const float4*)(vp + (long)c * 2048 + eq);
            sv[c*33+eq]=v4.x; sv[c*33+eq+1]=v4.y; sv[c*33+eq+2]=v4.z; sv[c*33+eq+3]=v4.w;
        }
        __syncthreads();

        if (tid < 64) {
            int d = tid;
            float acc = 0.f;
            for (int c = 0; c < 64; c++) {
                acc += sA[c*65 + d];
                sA[c*65 + d] = acc;
            }
            sGl[d] = acc;
        }
        __syncthreads();

#pragma unroll
        for (int w = 0; w < 8; w++) {
            int f = w * 512 + tid;
            int c = f >> 6;
            int d = f & 63;
            float G = sA[c*65 + d];
            sq[c*65 + d] *= __expf(G) * 0.125f;
            sk[c*65 + d] *= __expf(-G);
        }
        if (tid < 64) sGl[tid] = __expf(sGl[tid]);
        __syncthreads();

        float o_r[4];
#pragma unroll
        for (int j = 0; j < 4; j++) o_r[j] = 0.f;
        {
            const int c = cb;
#pragma unroll 4
            for (int d = 0; d < 64; d++) {
                float qv = sq[c*65 + d];
                const float* Srow = &sS[d*33 + eg*4];
#pragma unroll
                for (int j = 0; j < 4; j++) o_r[j] += qv * Srow[j];
            }
        }
        {
            const int c = cb;
            const int jbase = eg * 8;
            float a[8];
#pragma unroll
            for (int jj = 0; jj < 8; jj++) a[jj] = 0.f;
#pragma unroll 2
            for (int d = 0; d < 64; d++) {
                float qv = sq[c*65 + d];
#pragma unroll
                for (int jj = 0; jj < 8; jj++)
                    a[jj] += qv * sk[(jbase + jj)*65 + d];
            }
#pragma unroll
            for (int jj = 0; jj < 8; jj++)
                sA[c*65 + jbase + jj] = (jbase + jj <= c) ? a[jj] : 0.f;
        }
        __syncthreads();

        {
            const int c = cb;
            for (int j64 = 0; j64 <= c; j64++) {
                float a = sA[c*65 + j64];
                const float* vr = &sv[j64*33 + eg*4];
#pragma unroll
                for (int j = 0; j < 4; j++) o_r[j] += a * vr[j];
            }
            float* op = O + (base + (long)c * HH) * DVv + e0 + eg * 4;
            *(float4*)(op) = make_float4(o_r[0], o_r[1], o_r[2], o_r[3]);
        }
        {
            const int d = cb;
            float* Srow = &sS[d*33 + eg*4];
            float acc[4];
#pragma unroll
            for (int j = 0; j < 4; j++) acc[j] = Srow[j];
#pragma unroll 4
            for (int c64 = 0; c64 < 64; c64++) {
                float kv = sk[c64*65 + d];
                const float* vr = &sv[c64*33 + eg*4];
#pragma unroll
                for (int j = 0; j < 4; j++) acc[j] += kv * vr[j];
            }
            float eGl = sGl[d];
#pragma unroll
            for (int j = 0; j < 4; j++) Srow[j] = acc[j] * eGl;
        }
    }
}

// ---------------- RMS norm + sigmoid gate, in-place tf32 + permuted ----------
__global__ __launch_bounds__(256) void rmsgate_kernel(
    float* __restrict__ O, const float* __restrict__ G,
    const float* __restrict__ gw)
{
    int row = blockIdx.x * 8 + (threadIdx.x >> 5);   // (b*T+t)*16 + h
    int lane = threadIdx.x & 31;
    long basei = (long)row * 128 + lane * 4;
    float4 o4 = *(float4*)&O[basei];
    float ss = o4.x*o4.x + o4.y*o4.y + o4.z*o4.z + o4.w*o4.w;
    ss += __shfl_xor_sync(0xffffffffu, ss, 16);
    ss += __shfl_xor_sync(0xffffffffu, ss, 8);
    ss += __shfl_xor_sync(0xffffffffu, ss, 4);
    ss += __shfl_xor_sync(0xffffffffu, ss, 2);
    ss += __shfl_xor_sync(0xffffffffu, ss, 1);
    float rr = rsqrtf(ss * (1.f / 128.f) + EPSL);
    float4 g4 = *(const float4*)&G[basei];
    float4 w4 = *(const float4*)&gw[lane * 4];
    float r0 = f2tf32(o4.x * rr * w4.x / (1.f + __expf(-g4.x)));
    float r1 = f2tf32(o4.y * rr * w4.y / (1.f + __expf(-g4.y)));
    float r2 = f2tf32(o4.z * rr * w4.z / (1.f + __expf(-g4.z)));
    float r3 = f2tf32(o4.w * rr * w4.w / (1.f + __expf(-g4.w)));
    long obase = (long)(row >> 4) * 2048 + ((row & 15) * 4 + (lane >> 3)) * 32 + (lane & 7);
    O[obase + 0 ] = r0;
    O[obase + 8 ] = r1;
    O[obase + 16] = r2;
    O[obase + 24] = r3;
}

// ---------------- launch ----------------
extern "C" void kernel_launch(void* const* d_in, const int* in_sizes, int n_in,
                              void* d_out, int out_size)
{
    const float* hs    = (const float*)d_in[0];
    const float* Wq    = (const float*)d_in[1];
    const float* Wk    = (const float*)d_in[2];
    const float* Wv    = (const float*)d_in[3];
    const float* Wgk1  = (const float*)d_in[4];
    const float* Wgk2  = (const float*)d_in[5];
    const float* bgk2  = (const float*)d_in[6];
    const float* Wg1   = (const float*)d_in[7];
    const float* Wg2   = (const float*)d_in[8];
    const float* bg2   = (const float*)d_in[9];
    const float* Wo    = (const float*)d_in[10];
    const float* gnw   = (const float*)d_in[11];
    float* out = (float*)d_out;

    float *pq, *pk, *pv, *pgk, *pr1, *pr2, *pg, *po;
    float *phsr, *pwqr, *pwkr, *pwvr, *pwor;
    cudaGetSymbolAddress((void**)&pq,  g_q);
    cudaGetSymbolAddress((void**)&pk,  g_k);
    cudaGetSymbolAddress((void**)&pv,  g_v);
    cudaGetSymbolAddress((void**)&pgk, g_gk);
    cudaGetSymbolAddress((void**)&pr1, g_r1);
    cudaGetSymbolAddress((void**)&pr2, g_r2);
    cudaGetSymbolAddress((void**)&pg,  g_g);
    cudaGetSymbolAddress((void**)&po,  g_o);
    cudaGetSymbolAddress((void**)&phsr, g_hsr);
    cudaGetSymbolAddress((void**)&pwqr, g_wqr);
    cudaGetSymbolAddress((void**)&pwkr, g_wkr);
    cudaGetSymbolAddress((void**)&pwvr, g_wvr);
    cudaGetSymbolAddress((void**)&pwor, g_wor);

    cudaFuncSetAttribute(tf32gemm_qkv_kernel, cudaFuncAttributeMaxDynamicSharedMemorySize, QSM_BYTES);
    cudaFuncSetAttribute(tf32gemm4_kernel,    cudaFuncAttributeMaxDynamicSharedMemorySize, PSM_BYTES);
    cudaFuncSetAttribute(gla_kernel, cudaFuncAttributeMaxDynamicSharedMemorySize, SM_BYTES);

    // launch 0: round+permute hs
    round_perm_kernel<<<(MM*DD/4 + 255)/256, 256>>>(hs, phsr, MM*DD/4, DD);
    // launch 1: all weight transposes
    {
        dim3 blk(32, 8);
        transpose_perm_all_kernel<<<dim3(64, 64, 4), blk>>>(
            Wq, Wk, Wv, Wo, pwqr, pwkr, pwvr, pwor);
    }
    // launch 2: fused low-rank stage 1
    lowrank1_fused_kernel<<<MM / 8, 256>>>(hs, Wgk1, Wg1, pr1, pr2, DD);
    // launch 3: gk gate
    lowrank2_kernel<<<(MM * NQK) / 256, 256>>>(pr1, Wgk2, bgk2, pgk, NQK, 1);
    // launch 4 (ncu-captured): merged q/k/v projections
    tf32gemm_qkv_kernel<<<dim3(32, 32), 512, QSM_BYTES>>>(
        phsr, pwqr, pwkr, pwvr, pq, pk, pv);
    // launch 5: output gate
    lowrank2_kernel<<<(MM * NV) / 256, 256>>>(pr2, Wg2, bg2, pg, NV, 0);
    // launch 6: chunked GLA
    gla_kernel<<<BB * HH * 4, 512, SM_BYTES>>>(pq, pk, pv, pgk, po);
    // launch 7: rms norm + gate (permuted tf32 out)
    rmsgate_kernel<<<(MM * HH) / 8, 256>>>(po, pg, gnw);
    // launch 8: output projection
    {
        dim3 grid(DD / 256, MM / 128);
        tf32gemm4_kernel<<<grid, 512, PSM_BYTES>>>(po, pwor, out, MM, DD, NV);
    }
    (void)in_sizes; (void)n_in; (void)out_size;
}

// round 11
// speedup vs baseline: 1.5770x; 1.5770x over previous
#include <cuda_runtime.h>
#include <cuda_bf16.h>
#include <math.h>
#include <stdint.h>

// Problem constants
#define BB 2
#define TT 2048
#define DD 2048
#define HH 16
#define DKq 64
#define DVv 128
#define RR 16
#define CC 64
#define NCC 32
#define MM (BB*TT)          // 4096
#define NQK (HH*DKq)        // 1024
#define NV  (HH*DVv)        // 2048
#define GLN_INV (1.0f/16.0f)
#define EPSL 1e-5f

// ---------------- scratch (device globals, no allocs allowed) ----------------
__device__ float g_q [MM*NQK];
__device__ float g_k [MM*NQK];
__device__ float g_v [MM*NV];
__device__ float g_gk[MM*NQK];
__device__ float g_r1[MM*RR];
__device__ float g_r2[MM*RR];
__device__ float g_g [MM*NV];
__device__ float g_o [MM*NV];
__device__ float g_hsr[MM*DD];     // tf32-rounded + permuted hs
__device__ float g_wqr[DD*NQK];    // transposed [N][K] + permuted + rounded
__device__ float g_wkr[DD*NQK];
__device__ float g_wvr[DD*NV];
__device__ float g_wor[NV*DD];

// ---------------- helpers ----------------
__device__ __forceinline__ float f2tf32(float x) {
    uint32_t r;
    asm("cvt.rna.tf32.f32 %0, %1;" : "=r"(r) : "f"(x));
    return __uint_as_float(r);
}

__device__ __forceinline__ void cp16(void* smem_dst, const void* gmem_src) {
    uint32_t s = (uint32_t)__cvta_generic_to_shared(smem_dst);
    asm volatile("cp.async.cg.shared.global [%0], [%1], 16;" :: "r"(s), "l"(gmem_src));
}

// permutation within each 32-float K block: p(c) = (c&3)*8 + (c>>2)
// inverse: c(p) = (p&7)*4 + (p>>3)

// round hs to tf32 + permute
__global__ __launch_bounds__(256) void round_perm_kernel(
    const float* __restrict__ src, float* __restrict__ dst, int n4, int Kdim)
{
    int idx = blockIdx.x * 256 + threadIdx.x;
    if (idx >= n4) return;
    int q4 = Kdim >> 2;
    int m = idx / q4;
    int q = idx - m * q4;
    int kb = q >> 3;
    int j  = q & 7;
    const float* s = src + (long)m * Kdim + kb * 32;
    float4 o;
    int p0 = 4 * j;
    o.x = f2tf32(s[((p0    ) & 7) * 4 + ((p0    ) >> 3)]);
    o.y = f2tf32(s[((p0 + 1) & 7) * 4 + ((p0 + 1) >> 3)]);
    o.z = f2tf32(s[((p0 + 2) & 7) * 4 + ((p0 + 2) >> 3)]);
    o.w = f2tf32(s[((p0 + 3) & 7) * 4 + ((p0 + 3) >> 3)]);
    *(float4*)(dst + (long)m * Kdim + kb * 32 + p0) = o;
}

// merged transpose + round + permute for all 4 weights (z selects matrix)
__global__ __launch_bounds__(256) void transpose_perm_all_kernel(
    const float* __restrict__ Wq, const float* __restrict__ Wk,
    const float* __restrict__ Wv, const float* __restrict__ Wo,
    float* __restrict__ WTq, float* __restrict__ WTk,
    float* __restrict__ WTv, float* __restrict__ WTo)
{
    const float* W; float* WT; int K, N;
    switch (blockIdx.z) {
        case 0: W = Wq; WT = WTq; K = DD; N = NQK; break;
        case 1: W = Wk; WT = WTk; K = DD; N = NQK; break;
        case 2: W = Wv; WT = WTv; K = DD; N = NV;  break;
        default:W = Wo; WT = WTo; K = NV; N = DD;  break;
    }
    const int n0 = blockIdx.x * 32;
    const int k0 = blockIdx.y * 32;
    if (n0 >= N || k0 >= K) return;

    __shared__ float t[32][33];
    const int tx = threadIdx.x;       // 0..31
    const int ty = threadIdx.y;       // 0..7
#pragma unroll
    for (int i = 0; i < 4; i++)
        t[ty + 8*i][tx] = W[(long)(k0 + ty + 8*i) * N + n0 + tx];
    __syncthreads();
    int p0 = 4 * ty;
    float4 o;
    o.x = f2tf32(t[((p0    ) & 7) * 4 + ((p0    ) >> 3)][tx]);
    o.y = f2tf32(t[((p0 + 1) & 7) * 4 + ((p0 + 1) >> 3)][tx]);
    o.z = f2tf32(t[((p0 + 2) & 7) * 4 + ((p0 + 2) >> 3)][tx]);
    o.w = f2tf32(t[((p0 + 3) & 7) * 4 + ((p0 + 3) >> 3)][tx]);
    *(float4*)(WT + (long)(n0 + tx) * K + k0 + p0) = o;
}

// ---------------- tf32 mma.sync GEMM v4 (R9 config) ----------------
// C = act(A'[M,K] @ BT'[N,K]^T), operands in permuted tf32 layout.
// BM=128, BN=256, BK=32. 512 threads (16 warps), warp tile 32x64.
// 3-stage cp.async ring; rows 128B, 16B chunks swizzled by j^(row&7).
#define PSTAGE_A (128*32)
#define PSTAGE_B (256*32)
#define PSTAGE_FLOATS (PSTAGE_A + PSTAGE_B)   // 12288
#define PSM_BYTES (3*PSTAGE_FLOATS*4)         // 147456

// Core tile routine shared by both GEMM entry points.
template<bool SILU>
__device__ __forceinline__ void gemm_v4_body(
    const float* __restrict__ A, const float* __restrict__ BT,
    float* __restrict__ C, int N, int K, int bm, int bn, float* sm)
{
    const int tid  = threadIdx.x;
    const int warp = tid >> 5;
    const int lane = tid & 31;
    const int g    = lane >> 2;          // 0..7
    const int tig  = lane & 3;           // 0..3
    const int wm   = (warp >> 2) * 32;   // 0,32,64,96
    const int wn   = (warp & 3) * 64;    // 0,64,128,192
    const int NIT  = K >> 5;

    float c[2][8][4];
#pragma unroll
    for (int mt = 0; mt < 2; mt++)
#pragma unroll
        for (int nt = 0; nt < 8; nt++)
#pragma unroll
            for (int r = 0; r < 4; r++) c[mt][nt][r] = 0.f;

    auto fill = [&](int t) {
        char* As = (char*)(sm + (t % 3) * PSTAGE_FLOATS);
        char* Bs = As + PSTAGE_A * 4;
        const int kbase = t << 5;
#pragma unroll
        for (int i = 0; i < 2; i++) {
            int idx = tid + i * 512;
            int row = idx >> 3;
            int j   = idx & 7;
            cp16(As + row * 128 + ((j ^ (row & 7)) << 4),
                 A + (long)(bm + row) * K + kbase + j * 4);
        }
#pragma unroll
        for (int i = 0; i < 4; i++) {
            int idx = tid + i * 512;
            int row = idx >> 3;
            int j   = idx & 7;
            cp16(Bs + row * 128 + ((j ^ (row & 7)) << 4),
                 BT + (long)(bn + row) * K + kbase + j * 4);
        }
        asm volatile("cp.async.commit_group;");
    };

    fill(0); fill(1); fill(2);

    for (int t = 0; t < NIT; t++) {
        int rem = NIT - 1 - t;
        if (rem >= 2)      asm volatile("cp.async.wait_group 2;");
        else if (rem == 1) asm volatile("cp.async.wait_group 1;");
        else               asm volatile("cp.async.wait_group 0;");
        __syncthreads();

        const char* Ab = (const char*)(sm + (t % 3) * PSTAGE_FLOATS);
        const char* Bb = Ab + PSTAGE_A * 4;

#pragma unroll
        for (int h = 0; h < 2; h++) {
            const int ch = ((2 * tig + h) ^ g) << 4;
            float4 av[2][2];
#pragma unroll
            for (int mt = 0; mt < 2; mt++) {
                int r1 = wm + mt * 16 + g;
                av[mt][0] = *(const float4*)(Ab + r1 * 128 + ch);
                av[mt][1] = *(const float4*)(Ab + (r1 + 8) * 128 + ch);
            }
#pragma unroll
            for (int ntp = 0; ntp < 4; ntp++) {
                float4 bv[2];
#pragma unroll
                for (int u = 0; u < 2; u++) {
                    int rn = wn + (ntp * 2 + u) * 8 + g;
                    bv[u] = *(const float4*)(Bb + rn * 128 + ch);
                }
#pragma unroll
                for (int u = 0; u < 2; u++) {
                    int nt = ntp * 2 + u;
#pragma unroll
                    for (int mt = 0; mt < 2; mt++) {
                        asm volatile(
                            "mma.sync.aligned.m16n8k8.row.col.f32.tf32.tf32.f32 "
                            "{%0,%1,%2,%3}, {%4,%5,%6,%7}, {%8,%9}, {%0,%1,%2,%3};"
                            : "+f"(c[mt][nt][0]), "+f"(c[mt][nt][1]),
                              "+f"(c[mt][nt][2]), "+f"(c[mt][nt][3])
                            : "r"(__float_as_uint(av[mt][0].x)), "r"(__float_as_uint(av[mt][1].x)),
                              "r"(__float_as_uint(av[mt][0].y)), "r"(__float_as_uint(av[mt][1].y)),
                              "r"(__float_as_uint(bv[u].x)), "r"(__float_as_uint(bv[u].y)));
                        asm volatile(
                            "mma.sync.aligned.m16n8k8.row.col.f32.tf32.tf32.f32 "
                            "{%0,%1,%2,%3}, {%4,%5,%6,%7}, {%8,%9}, {%0,%1,%2,%3};"
                            : "+f"(c[mt][nt][0]), "+f"(c[mt][nt][1]),
                              "+f"(c[mt][nt][2]), "+f"(c[mt][nt][3])
                            : "r"(__float_as_uint(av[mt][0].z)), "r"(__float_as_uint(av[mt][1].z)),
                              "r"(__float_as_uint(av[mt][0].w)), "r"(__float_as_uint(av[mt][1].w)),
                              "r"(__float_as_uint(bv[u].z)), "r"(__float_as_uint(bv[u].w)));
                    }
                }
            }
        }
        __syncthreads();
        if (t + 3 < NIT) fill(t + 3);
    }

    // epilogue
#pragma unroll
    for (int mt = 0; mt < 2; mt++) {
        int r0 = bm + wm + mt * 16 + g;
#pragma unroll
        for (int nt = 0; nt < 8; nt++) {
            int col = bn + wn + nt * 8 + tig * 2;
            float x0 = c[mt][nt][0], x1 = c[mt][nt][1];
            float x2 = c[mt][nt][2], x3 = c[mt][nt][3];
            if (SILU) {
                x0 = x0 / (1.f + __expf(-x0));
                x1 = x1 / (1.f + __expf(-x1));
                x2 = x2 / (1.f + __expf(-x2));
                x3 = x3 / (1.f + __expf(-x3));
            }
            *(float2*)(C + (long)r0 * N + col)       = make_float2(x0, x1);
            *(float2*)(C + (long)(r0 + 8) * N + col) = make_float2(x2, x3);
        }
    }
}

// All three projections in one launch: grid (8, 32, 2).
// z=0: x<4 -> q tile x, x>=4 -> k tile x-4 (N=1024). z=1: v tile x (N=2048).
__global__ __launch_bounds__(512, 1) void tf32gemm_proj_kernel(
    const float* __restrict__ A,
    const float* __restrict__ BTq, const float* __restrict__ BTk,
    const float* __restrict__ BTv,
    float* __restrict__ Cq, float* __restrict__ Ck, float* __restrict__ Cv)
{
    extern __shared__ float sm[];
    const float* BT; float* C; int N; int bn;
    if (blockIdx.z == 0) {
        if (blockIdx.x < 4) { BT = BTq; C = Cq; N = NQK; bn = blockIdx.x * 256; }
        else                { BT = BTk; C = Ck; N = NQK; bn = (blockIdx.x - 4) * 256; }
    } else {
        BT = BTv; C = Cv; N = NV; bn = blockIdx.x * 256;
    }
    gemm_v4_body<true>(A, BT, C, N, DD, blockIdx.y * 128, bn, sm);
}

// Output projection (no activation).
__global__ __launch_bounds__(512, 1) void tf32gemm_out_kernel(
    const float* __restrict__ A, const float* __restrict__ BT,
    float* __restrict__ C)
{
    extern __shared__ float sm[];
    gemm_v4_body<false>(A, BT, C, DD, NV, blockIdx.y * 128, blockIdx.x * 256, sm);
}

// ---------------- fused low-rank stage 1: both gates, hs read once ----------
__global__ __launch_bounds__(256) void lowrank1_fused_kernel(
    const float* __restrict__ A, const float* __restrict__ W1,
    const float* __restrict__ W2, float* __restrict__ R1,
    float* __restrict__ R2, int K)
{
    const int warp = threadIdx.x >> 5;
    const int lane = threadIdx.x & 31;
    const int m = blockIdx.x * 8 + warp;
    const float* ap = A + (long)m * K;

    float acc1[16], acc2[16];
#pragma unroll
    for (int n = 0; n < 16; n++) { acc1[n] = 0.f; acc2[n] = 0.f; }

    for (int k = lane; k < K; k += 32) {
        float a = ap[k];
        const float4* w1 = (const float4*)(W1 + (long)k * 16);
        const float4* w2 = (const float4*)(W2 + (long)k * 16);
#pragma unroll
        for (int q = 0; q < 4; q++) {
            float4 u = w1[q];
            acc1[q*4+0] += a * u.x; acc1[q*4+1] += a * u.y;
            acc1[q*4+2] += a * u.z; acc1[q*4+3] += a * u.w;
            float4 v = w2[q];
            acc2[q*4+0] += a * v.x; acc2[q*4+1] += a * v.y;
            acc2[q*4+2] += a * v.z; acc2[q*4+3] += a * v.w;
        }
    }
#pragma unroll
    for (int n = 0; n < 16; n++) {
        float v = acc1[n];
        v += __shfl_xor_sync(0xffffffffu, v, 16);
        v += __shfl_xor_sync(0xffffffffu, v, 8);
        v += __shfl_xor_sync(0xffffffffu, v, 4);
        v += __shfl_xor_sync(0xffffffffu, v, 2);
        v += __shfl_xor_sync(0xffffffffu, v, 1);
        if (lane == 0) R1[(long)m * 16 + n] = v;
        float w = acc2[n];
        w += __shfl_xor_sync(0xffffffffu, w, 16);
        w += __shfl_xor_sync(0xffffffffu, w, 8);
        w += __shfl_xor_sync(0xffffffffu, w, 4);
        w += __shfl_xor_sync(0xffffffffu, w, 2);
        w += __shfl_xor_sync(0xffffffffu, w, 1);
        if (lane == 0) R2[(long)m * 16 + n] = w;
    }
}

// ---------------- low-rank stage 2 ----------------
__global__ __launch_bounds__(256) void lowrank2_kernel(
    const float* __restrict__ Rt, const float* __restrict__ W2,
    const float* __restrict__ bias, float* __restrict__ Out,
    int NOUT, int mode)
{
    int idx = blockIdx.x * 256 + threadIdx.x;
    int m = idx / NOUT;
    int n = idx - m * NOUT;
    const float* r = Rt + (long)m * 16;
    float acc = bias[n];
#pragma unroll
    for (int j = 0; j < 16; j++) acc += r[j] * W2[(long)j * NOUT + n];
    if (mode) {
        float x = acc;
        float ls = (x >= 0.f) ? -log1pf(__expf(-x)) : (x - log1pf(__expf(x)));
        acc = ls * GLN_INV;
    }
    Out[idx] = acc;
}

// ---------------- GLA chunked recurrence (512 threads) ----------------
#define OFF_Q  0
#define OFF_K  4160
#define OFF_A  8320
#define OFF_V  12480
#define OFF_S  14592
#define OFF_GL 16704
#define SM_FLOATS 16768
#define SM_BYTES  (SM_FLOATS * 4)

__global__ __launch_bounds__(512) void gla_kernel(
    const float* __restrict__ Q, const float* __restrict__ Kx,
    const float* __restrict__ V, const float* __restrict__ GK,
    float* __restrict__ O)
{
    extern __shared__ float sm[];
    float* sq  = sm + OFF_Q;
    float* sk  = sm + OFF_K;
    float* sA  = sm + OFF_A;
    float* sv  = sm + OFF_V;
    float* sS  = sm + OFF_S;
    float* sGl = sm + OFF_GL;

    const int tid = threadIdx.x;
    const int s  = blockIdx.x & 3;
    const int bh = blockIdx.x >> 2;
    const int h  = bh & 15;
    const int b  = bh >> 4;
    const int e0 = s * 32;

    const int cb = tid & 63;
    const int eg = tid >> 6;

    for (int i = tid; i < 64 * 33; i += 512) sS[i] = 0.f;

    for (int ch = 0; ch < NCC; ch++) {
        __syncthreads();
        const long base = ((long)(b * TT + ch * 64) * HH + h);
        const float* qp  = Q  + base * DKq;
        const float* kp  = Kx + base * DKq;
        const float* gp  = GK + base * DKq;
        const float* vp  = V  + base * DVv + e0;

#pragma unroll
        for (int w = 0; w < 2; w++) {
            int f = w * 512 + tid;
            int c = f >> 4;
            int dq = (f & 15) << 2;
            float4 a4 = *(const float4*)(qp + (long)c * 1024 + dq);
            sq[c*65+dq]=a4.x; sq[c*65+dq+1]=a4.y; sq[c*65+dq+2]=a4.z; sq[c*65+dq+3]=a4.w;
            float4 b4 = *(const float4*)(kp + (long)c * 1024 + dq);
            sk[c*65+dq]=b4.x; sk[c*65+dq+1]=b4.y; sk[c*65+dq+2]=b4.z; sk[c*65+dq+3]=b4.w;
            float4 g4 = *(const float4*)(gp + (long)c * 1024 + dq);
            sA[c*65+dq]=g4.x; sA[c*65+dq+1]=g4.y; sA[c*65+dq+2]=g4.z; sA[c*65+dq+3]=g4.w;
        }
        {
            int f = tid;
            int c = f >> 3;
            int eq = (f & 7) << 2;
            float4 v4 = *(const float4*)(vp + (long)c * 2048 + eq);
            sv[c*33+eq]=v4.x; sv[c*33+eq+1]=v4.y; sv[c*33+eq+2]=v4.z; sv[c*33+eq+3]=v4.w;
        }
        __syncthreads();

        if (tid < 64) {
            int d = tid;
            float acc = 0.f;
            for (int c = 0; c < 64; c++) {
                acc += sA[c*65 + d];
                sA[c*65 + d] = acc;
            }
            sGl[d] = acc;
        }
        __syncthreads();

#pragma unroll
        for (int w = 0; w < 8; w++) {
            int f = w * 512 + tid;
            int c = f >> 6;
            int d = f & 63;
            float G = sA[c*65 + d];
            sq[c*65 + d] *= __expf(G) * 0.125f;
            sk[c*65 + d] *= __expf(-G);
        }
        if (tid < 64) sGl[tid] = __expf(sGl[tid]);
        __syncthreads();

        float o_r[4];
#pragma unroll
        for (int j = 0; j < 4; j++) o_r[j] = 0.f;
        {
            const int c = cb;
#pragma unroll 4
            for (int d = 0; d < 64; d++) {
                float qv = sq[c*65 + d];
                const float* Srow = &sS[d*33 + eg*4];
#pragma unroll
                for (int j = 0; j < 4; j++) o_r[j] += qv * Srow[j];
            }
        }
        {
            const int c = cb;
            const int jbase = eg * 8;
            float a[8];
#pragma unroll
            for (int jj = 0; jj < 8; jj++) a[jj] = 0.f;
#pragma unroll 2
            for (int d = 0; d < 64; d++) {
                float qv = sq[c*65 + d];
#pragma unroll
                for (int jj = 0; jj < 8; jj++)
                    a[jj] += qv * sk[(jbase + jj)*65 + d];
            }
#pragma unroll
            for (int jj = 0; jj < 8; jj++)
                sA[c*65 + jbase + jj] = (jbase + jj <= c) ? a[jj] : 0.f;
        }
        __syncthreads();

        {
            const int c = cb;
            for (int j64 = 0; j64 <= c; j64++) {
                float a = sA[c*65 + j64];
                const float* vr = &sv[j64*33 + eg*4];
#pragma unroll
                for (int j = 0; j < 4; j++) o_r[j] += a * vr[j];
            }
            float* op = O + (base + (long)c * HH) * DVv + e0 + eg * 4;
            *(float4*)(op) = make_float4(o_r[0], o_r[1], o_r[2], o_r[3]);
        }
        {
            const int d = cb;
            float* Srow = &sS[d*33 + eg*4];
            float acc[4];
#pragma unroll
            for (int j = 0; j < 4; j++) acc[j] = Srow[j];
#pragma unroll 4
            for (int c64 = 0; c64 < 64; c64++) {
                float kv = sk[c64*65 + d];
                const float* vr = &sv[c64*33 + eg*4];
#pragma unroll
                for (int j = 0; j < 4; j++) acc[j] += kv * vr[j];
            }
            float eGl = sGl[d];
#pragma unroll
            for (int j = 0; j < 4; j++) Srow[j] = acc[j] * eGl;
        }
    }
}

// ---------------- RMS norm + sigmoid gate, in-place tf32 + permuted ----------
__global__ __launch_bounds__(256) void rmsgate_kernel(
    float* __restrict__ O, const float* __restrict__ G,
    const float* __restrict__ gw)
{
    int row = blockIdx.x * 8 + (threadIdx.x >> 5);   // (b*T+t)*16 + h
    int lane = threadIdx.x & 31;
    long basei = (long)row * 128 + lane * 4;
    float4 o4 = *(float4*)&O[basei];
    float ss = o4.x*o4.x + o4.y*o4.y + o4.z*o4.z + o4.w*o4.w;
    ss += __shfl_xor_sync(0xffffffffu, ss, 16);
    ss += __shfl_xor_sync(0xffffffffu, ss, 8);
    ss += __shfl_xor_sync(0xffffffffu, ss, 4);
    ss += __shfl_xor_sync(0xffffffffu, ss, 2);
    ss += __shfl_xor_sync(0xffffffffu, ss, 1);
    float rr = rsqrtf(ss * (1.f / 128.f) + EPSL);
    float4 g4 = *(const float4*)&G[basei];
    float4 w4 = *(const float4*)&gw[lane * 4];
    float r0 = f2tf32(o4.x * rr * w4.x / (1.f + __expf(-g4.x)));
    float r1 = f2tf32(o4.y * rr * w4.y / (1.f + __expf(-g4.y)));
    float r2 = f2tf32(o4.z * rr * w4.z / (1.f + __expf(-g4.z)));
    float r3 = f2tf32(o4.w * rr * w4.w / (1.f + __expf(-g4.w)));
    long obase = (long)(row >> 4) * 2048 + ((row & 15) * 4 + (lane >> 3)) * 32 + (lane & 7);
    O[obase + 0 ] = r0;
    O[obase + 8 ] = r1;
    O[obase + 16] = r2;
    O[obase + 24] = r3;
}

// ---------------- launch ----------------
extern "C" void kernel_launch(void* const* d_in, const int* in_sizes, int n_in,
                              void* d_out, int out_size)
{
    const float* hs    = (const float*)d_in[0];
    const float* Wq    = (const float*)d_in[1];
    const float* Wk    = (const float*)d_in[2];
    const float* Wv    = (const float*)d_in[3];
    const float* Wgk1  = (const float*)d_in[4];
    const float* Wgk2  = (const float*)d_in[5];
    const float* bgk2  = (const float*)d_in[6];
    const float* Wg1   = (const float*)d_in[7];
    const float* Wg2   = (const float*)d_in[8];
    const float* bg2   = (const float*)d_in[9];
    const float* Wo    = (const float*)d_in[10];
    const float* gnw   = (const float*)d_in[11];
    float* out = (float*)d_out;

    float *pq, *pk, *pv, *pgk, *pr1, *pr2, *pg, *po;
    float *phsr, *pwqr, *pwkr, *pwvr, *pwor;
    cudaGetSymbolAddress((void**)&pq,  g_q);
    cudaGetSymbolAddress((void**)&pk,  g_k);
    cudaGetSymbolAddress((void**)&pv,  g_v);
    cudaGetSymbolAddress((void**)&pgk, g_gk);
    cudaGetSymbolAddress((void**)&pr1, g_r1);
    cudaGetSymbolAddress((void**)&pr2, g_r2);
    cudaGetSymbolAddress((void**)&pg,  g_g);
    cudaGetSymbolAddress((void**)&po,  g_o);
    cudaGetSymbolAddress((void**)&phsr, g_hsr);
    cudaGetSymbolAddress((void**)&pwqr, g_wqr);
    cudaGetSymbolAddress((void**)&pwkr, g_wkr);
    cudaGetSymbolAddress((void**)&pwvr, g_wvr);
    cudaGetSymbolAddress((void**)&pwor, g_wor);

    cudaFuncSetAttribute(tf32gemm_proj_kernel, cudaFuncAttributeMaxDynamicSharedMemorySize, PSM_BYTES);
    cudaFuncSetAttribute(tf32gemm_out_kernel,  cudaFuncAttributeMaxDynamicSharedMemorySize, PSM_BYTES);
    cudaFuncSetAttribute(gla_kernel, cudaFuncAttributeMaxDynamicSharedMemorySize, SM_BYTES);

    // 0: round+permute hs
    round_perm_kernel<<<(MM*DD/4 + 255)/256, 256>>>(hs, phsr, MM*DD/4, DD);
    // 1: all weight transposes (z selects matrix)
    {
        dim3 blk(32, 8);
        transpose_perm_all_kernel<<<dim3(64, 64, 4), blk>>>(
            Wq, Wk, Wv, Wo, pwqr, pwkr, pwvr, pwor);
    }
    // 2: fused low-rank stage 1
    lowrank1_fused_kernel<<<MM / 8, 256>>>(hs, Wgk1, Wg1, pr1, pr2, DD);
    // 3: gk gate
    lowrank2_kernel<<<(MM * NQK) / 256, 256>>>(pr1, Wgk2, bgk2, pgk, NQK, 1);
    // 4: output gate
    lowrank2_kernel<<<(MM * NV) / 256, 256>>>(pr2, Wg2, bg2, pg, NV, 0);
    // 5: all projections (q, k, v) in one launch — 512 CTAs
    tf32gemm_proj_kernel<<<dim3(8, 32, 2), 512, PSM_BYTES>>>(
        phsr, pwqr, pwkr, pwvr, pq, pk, pv);
    // 6: chunked GLA
    gla_kernel<<<BB * HH * 4, 512, SM_BYTES>>>(pq, pk, pv, pgk, po);
    // 7: rms norm + gate (writes permuted tf32 layout)
    rmsgate_kernel<<<(MM * HH) / 8, 256>>>(po, pg, gnw);
    // 8: output projection
    tf32gemm_out_kernel<<<dim3(DD / 256, MM / 128), 512, PSM_BYTES>>>(po, pwor, out);
    (void)in_sizes; (void)n_in; (void)out_size;
}

// round 12
// speedup vs baseline: 1.6641x; 1.0552x over previous
#include <cuda_runtime.h>
#include <cuda_bf16.h>
#include <math.h>
#include <stdint.h>

// Problem constants
#define BB 2
#define TT 2048
#define DD 2048
#define HH 16
#define DKq 64
#define DVv 128
#define RR 16
#define CC 64
#define NCC 32
#define MM (BB*TT)          // 4096
#define NQK (HH*DKq)        // 1024
#define NV  (HH*DVv)        // 2048
#define GLN_INV (1.0f/16.0f)
#define EPSL 1e-5f

// ---------------- scratch (device globals, no allocs allowed) ----------------
__device__ float g_q [MM*NQK];
__device__ float g_k [MM*NQK];
__device__ float g_v [MM*NV];
__device__ float g_gk[MM*NQK];
__device__ float g_r1[MM*RR];
__device__ float g_r2[MM*RR];
__device__ float g_g [MM*NV];
__device__ float g_o [MM*NV];
__device__ float g_hsr[MM*DD];     // tf32-rounded + permuted hs
__device__ float g_wqr[DD*NQK];    // transposed [N][K] + permuted + rounded
__device__ float g_wkr[DD*NQK];
__device__ float g_wvr[DD*NV];
__device__ float g_wor[NV*DD];

// ---------------- helpers ----------------
__device__ __forceinline__ float f2tf32(float x) {
    uint32_t r;
    asm("cvt.rna.tf32.f32 %0, %1;" : "=r"(r) : "f"(x));
    return __uint_as_float(r);
}

__device__ __forceinline__ void cp16(void* smem_dst, const void* gmem_src) {
    uint32_t s = (uint32_t)__cvta_generic_to_shared(smem_dst);
    asm volatile("cp.async.cg.shared.global [%0], [%1], 16;" :: "r"(s), "l"(gmem_src));
}

// permutation within each 32-float K block: p(c) = (c&3)*8 + (c>>2)
// inverse: c(p) = (p&7)*4 + (p>>3)

// round hs to tf32 + permute
__global__ __launch_bounds__(256) void round_perm_kernel(
    const float* __restrict__ src, float* __restrict__ dst, int n4, int Kdim)
{
    int idx = blockIdx.x * 256 + threadIdx.x;
    if (idx >= n4) return;
    int q4 = Kdim >> 2;
    int m = idx / q4;
    int q = idx - m * q4;
    int kb = q >> 3;
    int j  = q & 7;
    const float* s = src + (long)m * Kdim + kb * 32;
    float4 o;
    int p0 = 4 * j;
    o.x = f2tf32(s[((p0    ) & 7) * 4 + ((p0    ) >> 3)]);
    o.y = f2tf32(s[((p0 + 1) & 7) * 4 + ((p0 + 1) >> 3)]);
    o.z = f2tf32(s[((p0 + 2) & 7) * 4 + ((p0 + 2) >> 3)]);
    o.w = f2tf32(s[((p0 + 3) & 7) * 4 + ((p0 + 3) >> 3)]);
    *(float4*)(dst + (long)m * Kdim + kb * 32 + p0) = o;
}

// merged transpose + round + permute for all 4 weights (z selects matrix)
__global__ __launch_bounds__(256) void transpose_perm_all_kernel(
    const float* __restrict__ Wq, const float* __restrict__ Wk,
    const float* __restrict__ Wv, const float* __restrict__ Wo,
    float* __restrict__ WTq, float* __restrict__ WTk,
    float* __restrict__ WTv, float* __restrict__ WTo)
{
    const float* W; float* WT; int K, N;
    switch (blockIdx.z) {
        case 0: W = Wq; WT = WTq; K = DD; N = NQK; break;
        case 1: W = Wk; WT = WTk; K = DD; N = NQK; break;
        case 2: W = Wv; WT = WTv; K = DD; N = NV;  break;
        default:W = Wo; WT = WTo; K = NV; N = DD;  break;
    }
    const int n0 = blockIdx.x * 32;
    const int k0 = blockIdx.y * 32;
    if (n0 >= N || k0 >= K) return;

    __shared__ float t[32][33];
    const int tx = threadIdx.x;       // 0..31
    const int ty = threadIdx.y;       // 0..7
#pragma unroll
    for (int i = 0; i < 4; i++)
        t[ty + 8*i][tx] = W[(long)(k0 + ty + 8*i) * N + n0 + tx];
    __syncthreads();
    int p0 = 4 * ty;
    float4 o;
    o.x = f2tf32(t[((p0    ) & 7) * 4 + ((p0    ) >> 3)][tx]);
    o.y = f2tf32(t[((p0 + 1) & 7) * 4 + ((p0 + 1) >> 3)][tx]);
    o.z = f2tf32(t[((p0 + 2) & 7) * 4 + ((p0 + 2) >> 3)][tx]);
    o.w = f2tf32(t[((p0 + 3) & 7) * 4 + ((p0 + 3) >> 3)][tx]);
    *(float4*)(WT + (long)(n0 + tx) * K + k0 + p0) = o;
}

// ---------------- tf32 mma.sync GEMM v5 (single-sync pipeline) ---------------
// C = act(A'[M,K] @ BT'[N,K]^T), operands in permuted tf32 layout.
// BM=128, BN=256, BK=32. 512 threads (16 warps), warp tile 32x64.
// 3-stage cp.async ring, ONE __syncthreads per iteration.
#define PSTAGE_A (128*32)
#define PSTAGE_B (256*32)
#define PSTAGE_FLOATS (PSTAGE_A + PSTAGE_B)   // 12288
#define PSM_BYTES (3*PSTAGE_FLOATS*4)         // 147456

template<bool SILU>
__device__ __forceinline__ void gemm_v5_body(
    const float* __restrict__ A, const float* __restrict__ BT,
    float* __restrict__ C, int N, int K, int bm, int bn, float* sm)
{
    const int tid  = threadIdx.x;
    const int warp = tid >> 5;
    const int lane = tid & 31;
    const int g    = lane >> 2;          // 0..7
    const int tig  = lane & 3;           // 0..3
    const int wm   = (warp >> 2) * 32;   // 0,32,64,96
    const int wn   = (warp & 3) * 64;    // 0,64,128,192
    const int NIT  = K >> 5;

    float c[2][8][4];
#pragma unroll
    for (int mt = 0; mt < 2; mt++)
#pragma unroll
        for (int nt = 0; nt < 8; nt++)
#pragma unroll
            for (int r = 0; r < 4; r++) c[mt][nt][r] = 0.f;

    auto fill = [&](int t) {
        char* As = (char*)(sm + (t % 3) * PSTAGE_FLOATS);
        char* Bs = As + PSTAGE_A * 4;
        const int kbase = t << 5;
#pragma unroll
        for (int i = 0; i < 2; i++) {
            int idx = tid + i * 512;
            int row = idx >> 3;
            int j   = idx & 7;
            cp16(As + row * 128 + ((j ^ (row & 7)) << 4),
                 A + (long)(bm + row) * K + kbase + j * 4);
        }
#pragma unroll
        for (int i = 0; i < 4; i++) {
            int idx = tid + i * 512;
            int row = idx >> 3;
            int j   = idx & 7;
            cp16(Bs + row * 128 + ((j ^ (row & 7)) << 4),
                 BT + (long)(bn + row) * K + kbase + j * 4);
        }
        asm volatile("cp.async.commit_group;");
    };

    fill(0); fill(1);

    for (int t = 0; t < NIT; t++) {
        if (t + 1 < NIT) asm volatile("cp.async.wait_group 1;");
        else             asm volatile("cp.async.wait_group 0;");
        __syncthreads();   // single barrier per iteration

        const char* Ab = (const char*)(sm + (t % 3) * PSTAGE_FLOATS);
        const char* Bb = Ab + PSTAGE_A * 4;

#pragma unroll
        for (int h = 0; h < 2; h++) {
            const int ch = ((2 * tig + h) ^ g) << 4;
            float4 av[2][2];
#pragma unroll
            for (int mt = 0; mt < 2; mt++) {
                int r1 = wm + mt * 16 + g;
                av[mt][0] = *(const float4*)(Ab + r1 * 128 + ch);
                av[mt][1] = *(const float4*)(Ab + (r1 + 8) * 128 + ch);
            }
#pragma unroll
            for (int ntp = 0; ntp < 4; ntp++) {
                float4 bv[2];
#pragma unroll
                for (int u = 0; u < 2; u++) {
                    int rn = wn + (ntp * 2 + u) * 8 + g;
                    bv[u] = *(const float4*)(Bb + rn * 128 + ch);
                }
#pragma unroll
                for (int u = 0; u < 2; u++) {
                    int nt = ntp * 2 + u;
#pragma unroll
                    for (int mt = 0; mt < 2; mt++) {
                        asm volatile(
                            "mma.sync.aligned.m16n8k8.row.col.f32.tf32.tf32.f32 "
                            "{%0,%1,%2,%3}, {%4,%5,%6,%7}, {%8,%9}, {%0,%1,%2,%3};"
                            : "+f"(c[mt][nt][0]), "+f"(c[mt][nt][1]),
                              "+f"(c[mt][nt][2]), "+f"(c[mt][nt][3])
                            : "r"(__float_as_uint(av[mt][0].x)), "r"(__float_as_uint(av[mt][1].x)),
                              "r"(__float_as_uint(av[mt][0].y)), "r"(__float_as_uint(av[mt][1].y)),
                              "r"(__float_as_uint(bv[u].x)), "r"(__float_as_uint(bv[u].y)));
                        asm volatile(
                            "mma.sync.aligned.m16n8k8.row.col.f32.tf32.tf32.f32 "
                            "{%0,%1,%2,%3}, {%4,%5,%6,%7}, {%8,%9}, {%0,%1,%2,%3};"
                            : "+f"(c[mt][nt][0]), "+f"(c[mt][nt][1]),
                              "+f"(c[mt][nt][2]), "+f"(c[mt][nt][3])
                            : "r"(__float_as_uint(av[mt][0].z)), "r"(__float_as_uint(av[mt][1].z)),
                              "r"(__float_as_uint(av[mt][0].w)), "r"(__float_as_uint(av[mt][1].w)),
                              "r"(__float_as_uint(bv[u].z)), "r"(__float_as_uint(bv[u].w)));
                    }
                }
            }
        }
        // Safe without a second barrier: writes stage (t+2)%3 == (t-1)%3,
        // whose readers all passed the __syncthreads above.
        if (t + 2 < NIT) fill(t + 2);
    }

    // epilogue
#pragma unroll
    for (int mt = 0; mt < 2; mt++) {
        int r0 = bm + wm + mt * 16 + g;
#pragma unroll
        for (int nt = 0; nt < 8; nt++) {
            int col = bn + wn + nt * 8 + tig * 2;
            float x0 = c[mt][nt][0], x1 = c[mt][nt][1];
            float x2 = c[mt][nt][2], x3 = c[mt][nt][3];
            if (SILU) {
                x0 = x0 / (1.f + __expf(-x0));
                x1 = x1 / (1.f + __expf(-x1));
                x2 = x2 / (1.f + __expf(-x2));
                x3 = x3 / (1.f + __expf(-x3));
            }
            *(float2*)(C + (long)r0 * N + col)       = make_float2(x0, x1);
            *(float2*)(C + (long)(r0 + 8) * N + col) = make_float2(x2, x3);
        }
    }
}

// All three projections in one launch: grid (8, 32, 2).
__global__ __launch_bounds__(512, 1) void tf32gemm_proj_kernel(
    const float* __restrict__ A,
    const float* __restrict__ BTq, const float* __restrict__ BTk,
    const float* __restrict__ BTv,
    float* __restrict__ Cq, float* __restrict__ Ck, float* __restrict__ Cv)
{
    extern __shared__ float sm[];
    const float* BT; float* C; int N; int bn;
    if (blockIdx.z == 0) {
        if (blockIdx.x < 4) { BT = BTq; C = Cq; N = NQK; bn = blockIdx.x * 256; }
        else                { BT = BTk; C = Ck; N = NQK; bn = (blockIdx.x - 4) * 256; }
    } else {
        BT = BTv; C = Cv; N = NV; bn = blockIdx.x * 256;
    }
    gemm_v5_body<true>(A, BT, C, N, DD, blockIdx.y * 128, bn, sm);
}

// Output projection (no activation).
__global__ __launch_bounds__(512, 1) void tf32gemm_out_kernel(
    const float* __restrict__ A, const float* __restrict__ BT,
    float* __restrict__ C)
{
    extern __shared__ float sm[];
    gemm_v5_body<false>(A, BT, C, DD, NV, blockIdx.y * 128, blockIdx.x * 256, sm);
}

// ---------------- fused low-rank stage 1: both gates, hs read once ----------
__global__ __launch_bounds__(256) void lowrank1_fused_kernel(
    const float* __restrict__ A, const float* __restrict__ W1,
    const float* __restrict__ W2, float* __restrict__ R1,
    float* __restrict__ R2, int K)
{
    const int warp = threadIdx.x >> 5;
    const int lane = threadIdx.x & 31;
    const int m = blockIdx.x * 8 + warp;
    const float* ap = A + (long)m * K;

    float acc1[16], acc2[16];
#pragma unroll
    for (int n = 0; n < 16; n++) { acc1[n] = 0.f; acc2[n] = 0.f; }

    for (int k = lane; k < K; k += 32) {
        float a = ap[k];
        const float4* w1 = (const float4*)(W1 + (long)k * 16);
        const float4* w2 = (const float4*)(W2 + (long)k * 16);
#pragma unroll
        for (int q = 0; q < 4; q++) {
            float4 u = w1[q];
            acc1[q*4+0] += a * u.x; acc1[q*4+1] += a * u.y;
            acc1[q*4+2] += a * u.z; acc1[q*4+3] += a * u.w;
            float4 v = w2[q];
            acc2[q*4+0] += a * v.x; acc2[q*4+1] += a * v.y;
            acc2[q*4+2] += a * v.z; acc2[q*4+3] += a * v.w;
        }
    }
#pragma unroll
    for (int n = 0; n < 16; n++) {
        float v = acc1[n];
        v += __shfl_xor_sync(0xffffffffu, v, 16);
        v += __shfl_xor_sync(0xffffffffu, v, 8);
        v += __shfl_xor_sync(0xffffffffu, v, 4);
        v += __shfl_xor_sync(0xffffffffu, v, 2);
        v += __shfl_xor_sync(0xffffffffu, v, 1);
        if (lane == 0) R1[(long)m * 16 + n] = v;
        float w = acc2[n];
        w += __shfl_xor_sync(0xffffffffu, w, 16);
        w += __shfl_xor_sync(0xffffffffu, w, 8);
        w += __shfl_xor_sync(0xffffffffu, w, 4);
        w += __shfl_xor_sync(0xffffffffu, w, 2);
        w += __shfl_xor_sync(0xffffffffu, w, 1);
        if (lane == 0) R2[(long)m * 16 + n] = w;
    }
}

// ---------------- low-rank stage 2 v2: 4 outputs/thread ----------------
__global__ __launch_bounds__(256) void lowrank2_kernel(
    const float* __restrict__ Rt, const float* __restrict__ W2,
    const float* __restrict__ bias, float* __restrict__ Out,
    int NOUT, int mode)
{
    int idx = blockIdx.x * 256 + threadIdx.x;   // over M*NOUT/4
    int q4 = NOUT >> 2;
    int m = idx / q4;
    int n = (idx - m * q4) << 2;
    const float* r = Rt + (long)m * 16;
    float4 acc = *(const float4*)&bias[n];
#pragma unroll
    for (int j = 0; j < 16; j++) {
        float rv = r[j];
        float4 w = *(const float4*)&W2[(long)j * NOUT + n];
        acc.x += rv * w.x; acc.y += rv * w.y;
        acc.z += rv * w.z; acc.w += rv * w.w;
    }
    if (mode) {
        float x;
        x = acc.x; acc.x = ((x >= 0.f) ? -log1pf(__expf(-x)) : (x - log1pf(__expf(x)))) * GLN_INV;
        x = acc.y; acc.y = ((x >= 0.f) ? -log1pf(__expf(-x)) : (x - log1pf(__expf(x)))) * GLN_INV;
        x = acc.z; acc.z = ((x >= 0.f) ? -log1pf(__expf(-x)) : (x - log1pf(__expf(x)))) * GLN_INV;
        x = acc.w; acc.w = ((x >= 0.f) ? -log1pf(__expf(-x)) : (x - log1pf(__expf(x)))) * GLN_INV;
    }
    *(float4*)&Out[(long)idx * 4] = acc;
}

// ---------------- GLA chunked recurrence (512 threads) ----------------
#define OFF_Q  0
#define OFF_K  4160
#define OFF_A  8320
#define OFF_V  12480
#define OFF_S  14592
#define OFF_GL 16704
#define SM_FLOATS 16768
#define SM_BYTES  (SM_FLOATS * 4)

__global__ __launch_bounds__(512) void gla_kernel(
    const float* __restrict__ Q, const float* __restrict__ Kx,
    const float* __restrict__ V, const float* __restrict__ GK,
    float* __restrict__ O)
{
    extern __shared__ float sm[];
    float* sq  = sm + OFF_Q;
    float* sk  = sm + OFF_K;
    float* sA  = sm + OFF_A;
    float* sv  = sm + OFF_V;
    float* sS  = sm + OFF_S;
    float* sGl = sm + OFF_GL;

    const int tid = threadIdx.x;
    const int s  = blockIdx.x & 3;
    const int bh = blockIdx.x >> 2;
    const int h  = bh & 15;
    const int b  = bh >> 4;
    const int e0 = s * 32;

    const int cb = tid & 63;
    const int eg = tid >> 6;

    for (int i = tid; i < 64 * 33; i += 512) sS[i] = 0.f;

    for (int ch = 0; ch < NCC; ch++) {
        __syncthreads();
        const long base = ((long)(b * TT + ch * 64) * HH + h);
        const float* qp  = Q  + base * DKq;
        const float* kp  = Kx + base * DKq;
        const float* gp  = GK + base * DKq;
        const float* vp  = V  + base * DVv + e0;

#pragma unroll
        for (int w = 0; w < 2; w++) {
            int f = w * 512 + tid;
            int c = f >> 4;
            int dq = (f & 15) << 2;
            float4 a4 = *(const float4*)(qp + (long)c * 1024 + dq);
            sq[c*65+dq]=a4.x; sq[c*65+dq+1]=a4.y; sq[c*65+dq+2]=a4.z; sq[c*65+dq+3]=a4.w;
            float4 b4 = *(const float4*)(kp + (long)c * 1024 + dq);
            sk[c*65+dq]=b4.x; sk[c*65+dq+1]=b4.y; sk[c*65+dq+2]=b4.z; sk[c*65+dq+3]=b4.w;
            float4 g4 = *(const float4*)(gp + (long)c * 1024 + dq);
            sA[c*65+dq]=g4.x; sA[c*65+dq+1]=g4.y; sA[c*65+dq+2]=g4.z; sA[c*65+dq+3]=g4.w;
        }
        {
            int f = tid;
            int c = f >> 3;
            int eq = (f & 7) << 2;
            float4 v4 = *(const float4*)(vp + (long)c * 2048 + eq);
            sv[c*33+eq]=v4.x; sv[c*33+eq+1]=v4.y; sv[c*33+eq+2]=v4.z; sv[c*33+eq+3]=v4.w;
        }
        __syncthreads();

        if (tid < 64) {
            int d = tid;
            float acc = 0.f;
            for (int c = 0; c < 64; c++) {
                acc += sA[c*65 + d];
                sA[c*65 + d] = acc;
            }
            sGl[d] = acc;
        }
        __syncthreads();

#pragma unroll
        for (int w = 0; w < 8; w++) {
            int f = w * 512 + tid;
            int c = f >> 6;
            int d = f & 63;
            float G = sA[c*65 + d];
            sq[c*65 + d] *= __expf(G) * 0.125f;
            sk[c*65 + d] *= __expf(-G);
        }
        if (tid < 64) sGl[tid] = __expf(sGl[tid]);
        __syncthreads();

        float o_r[4];
#pragma unroll
        for (int j = 0; j < 4; j++) o_r[j] = 0.f;
        {
            const int c = cb;
#pragma unroll 4
            for (int d = 0; d < 64; d++) {
                float qv = sq[c*65 + d];
                const float* Srow = &sS[d*33 + eg*4];
#pragma unroll
                for (int j = 0; j < 4; j++) o_r[j] += qv * Srow[j];
            }
        }
        {
            const int c = cb;
            const int jbase = eg * 8;
            float a[8];
#pragma unroll
            for (int jj = 0; jj < 8; jj++) a[jj] = 0.f;
#pragma unroll 2
            for (int d = 0; d < 64; d++) {
                float qv = sq[c*65 + d];
#pragma unroll
                for (int jj = 0; jj < 8; jj++)
                    a[jj] += qv * sk[(jbase + jj)*65 + d];
            }
#pragma unroll
            for (int jj = 0; jj < 8; jj++)
                sA[c*65 + jbase + jj] = (jbase + jj <= c) ? a[jj] : 0.f;
        }
        __syncthreads();

        {
            const int c = cb;
            for (int j64 = 0; j64 <= c; j64++) {
                float a = sA[c*65 + j64];
                const float* vr = &sv[j64*33 + eg*4];
#pragma unroll
                for (int j = 0; j < 4; j++) o_r[j] += a * vr[j];
            }
            float* op = O + (base + (long)c * HH) * DVv + e0 + eg * 4;
            *(float4*)(op) = make_float4(o_r[0], o_r[1], o_r[2], o_r[3]);
        }
        {
            const int d = cb;
            float* Srow = &sS[d*33 + eg*4];
            float acc[4];
#pragma unroll
            for (int j = 0; j < 4; j++) acc[j] = Srow[j];
#pragma unroll 4
            for (int c64 = 0; c64 < 64; c64++) {
                float kv = sk[c64*65 + d];
                const float* vr = &sv[c64*33 + eg*4];
#pragma unroll
                for (int j = 0; j < 4; j++) acc[j] += kv * vr[j];
            }
            float eGl = sGl[d];
#pragma unroll
            for (int j = 0; j < 4; j++) Srow[j] = acc[j] * eGl;
        }
    }
}

// ---------------- RMS norm + sigmoid gate, in-place tf32 + permuted ----------
__global__ __launch_bounds__(256) void rmsgate_kernel(
    float* __restrict__ O, const float* __restrict__ G,
    const float* __restrict__ gw)
{
    int row = blockIdx.x * 8 + (threadIdx.x >> 5);   // (b*T+t)*16 + h
    int lane = threadIdx.x & 31;
    long basei = (long)row * 128 + lane * 4;
    float4 o4 = *(float4*)&O[basei];
    float ss = o4.x*o4.x + o4.y*o4.y + o4.z*o4.z + o4.w*o4.w;
    ss += __shfl_xor_sync(0xffffffffu, ss, 16);
    ss += __shfl_xor_sync(0xffffffffu, ss, 8);
    ss += __shfl_xor_sync(0xffffffffu, ss, 4);
    ss += __shfl_xor_sync(0xffffffffu, ss, 2);
    ss += __shfl_xor_sync(0xffffffffu, ss, 1);
    float rr = rsqrtf(ss * (1.f / 128.f) + EPSL);
    float4 g4 = *(const float4*)&G[basei];
    float4 w4 = *(const float4*)&gw[lane * 4];
    float r0 = f2tf32(o4.x * rr * w4.x / (1.f + __expf(-g4.x)));
    float r1 = f2tf32(o4.y * rr * w4.y / (1.f + __expf(-g4.y)));
    float r2 = f2tf32(o4.z * rr * w4.z / (1.f + __expf(-g4.z)));
    float r3 = f2tf32(o4.w * rr * w4.w / (1.f + __expf(-g4.w)));
    long obase = (long)(row >> 4) * 2048 + ((row & 15) * 4 + (lane >> 3)) * 32 + (lane & 7);
    O[obase + 0 ] = r0;
    O[obase + 8 ] = r1;
    O[obase + 16] = r2;
    O[obase + 24] = r3;
}

// ---------------- launch ----------------
extern "C" void kernel_launch(void* const* d_in, const int* in_sizes, int n_in,
                              void* d_out, int out_size)
{
    const float* hs    = (const float*)d_in[0];
    const float* Wq    = (const float*)d_in[1];
    const float* Wk    = (const float*)d_in[2];
    const float* Wv    = (const float*)d_in[3];
    const float* Wgk1  = (const float*)d_in[4];
    const float* Wgk2  = (const float*)d_in[5];
    const float* bgk2  = (const float*)d_in[6];
    const float* Wg1   = (const float*)d_in[7];
    const float* Wg2   = (const float*)d_in[8];
    const float* bg2   = (const float*)d_in[9];
    const float* Wo    = (const float*)d_in[10];
    const float* gnw   = (const float*)d_in[11];
    float* out = (float*)d_out;

    float *pq, *pk, *pv, *pgk, *pr1, *pr2, *pg, *po;
    float *phsr, *pwqr, *pwkr, *pwvr, *pwor;
    cudaGetSymbolAddress((void**)&pq,  g_q);
    cudaGetSymbolAddress((void**)&pk,  g_k);
    cudaGetSymbolAddress((void**)&pv,  g_v);
    cudaGetSymbolAddress((void**)&pgk, g_gk);
    cudaGetSymbolAddress((void**)&pr1, g_r1);
    cudaGetSymbolAddress((void**)&pr2, g_r2);
    cudaGetSymbolAddress((void**)&pg,  g_g);
    cudaGetSymbolAddress((void**)&po,  g_o);
    cudaGetSymbolAddress((void**)&phsr, g_hsr);
    cudaGetSymbolAddress((void**)&pwqr, g_wqr);
    cudaGetSymbolAddress((void**)&pwkr, g_wkr);
    cudaGetSymbolAddress((void**)&pwvr, g_wvr);
    cudaGetSymbolAddress((void**)&pwor, g_wor);

    cudaFuncSetAttribute(tf32gemm_proj_kernel, cudaFuncAttributeMaxDynamicSharedMemorySize, PSM_BYTES);
    cudaFuncSetAttribute(tf32gemm_out_kernel,  cudaFuncAttributeMaxDynamicSharedMemorySize, PSM_BYTES);
    cudaFuncSetAttribute(gla_kernel, cudaFuncAttributeMaxDynamicSharedMemorySize, SM_BYTES);

    // 0: round+permute hs
    round_perm_kernel<<<(MM*DD/4 + 255)/256, 256>>>(hs, phsr, MM*DD/4, DD);
    // 1: all weight transposes
    {
        dim3 blk(32, 8);
        transpose_perm_all_kernel<<<dim3(64, 64, 4), blk>>>(
            Wq, Wk, Wv, Wo, pwqr, pwkr, pwvr, pwor);
    }
    // 2: fused low-rank stage 1
    lowrank1_fused_kernel<<<MM / 8, 256>>>(hs, Wgk1, Wg1, pr1, pr2, DD);
    // 3 (ncu-captured): all projections (q, k, v) — 512 CTAs
    tf32gemm_proj_kernel<<<dim3(8, 32, 2), 512, PSM_BYTES>>>(
        phsr, pwqr, pwkr, pwvr, pq, pk, pv);
    // 4: gk gate
    lowrank2_kernel<<<(MM * NQK / 4) / 256, 256>>>(pr1, Wgk2, bgk2, pgk, NQK, 1);
    // 5: output gate
    lowrank2_kernel<<<(MM * NV / 4) / 256, 256>>>(pr2, Wg2, bg2, pg, NV, 0);
    // 6: chunked GLA
    gla_kernel<<<BB * HH * 4, 512, SM_BYTES>>>(pq, pk, pv, pgk, po);
    // 7: rms norm + gate (writes permuted tf32 layout)
    rmsgate_kernel<<<(MM * HH) / 8, 256>>>(po, pg, gnw);
    // 8: output projection
    tf32gemm_out_kernel<<<dim3(DD / 256, MM / 128), 512, PSM_BYTES>>>(po, pwor, out);
    (void)in_sizes; (void)n_in; (void)out_size;
}

// round 13
// speedup vs baseline: 1.7233x; 1.0356x over previous
#include <cuda_runtime.h>
#include <cuda_bf16.h>
#include <math.h>
#include <stdint.h>

// Problem constants
#define BB 2
#define TT 2048
#define DD 2048
#define HH 16
#define DKq 64
#define DVv 128
#define RR 16
#define CC 64
#define NCC 32
#define MM (BB*TT)          // 4096
#define NQK (HH*DKq)        // 1024
#define NV  (HH*DVv)        // 2048
#define GLN_INV (1.0f/16.0f)
#define EPSL 1e-5f

// ---------------- scratch (device globals, no allocs allowed) ----------------
__device__ float g_q [MM*NQK];
__device__ float g_k [MM*NQK];
__device__ float g_v [MM*NV];
__device__ float g_gk[MM*NQK];
__device__ float g_r1[MM*RR];
__device__ float g_r2[MM*RR];
__device__ float g_g [MM*NV];
__device__ float g_o [MM*NV];
__device__ float g_hsr[MM*DD];     // tf32-rounded + permuted hs
__device__ float g_wqr[DD*NQK];    // transposed [N][K] + permuted + rounded
__device__ float g_wkr[DD*NQK];
__device__ float g_wvr[DD*NV];
__device__ float g_wor[NV*DD];

// ---------------- helpers ----------------
__device__ __forceinline__ float f2tf32(float x) {
    uint32_t r;
    asm("cvt.rna.tf32.f32 %0, %1;" : "=r"(r) : "f"(x));
    return __uint_as_float(r);
}

__device__ __forceinline__ void cp16(void* smem_dst, const void* gmem_src) {
    uint32_t s = (uint32_t)__cvta_generic_to_shared(smem_dst);
    asm volatile("cp.async.cg.shared.global [%0], [%1], 16;" :: "r"(s), "l"(gmem_src));
}

// permutation within each 32-float K block: p(c) = (c&3)*8 + (c>>2)
// inverse: c(p) = (p&7)*4 + (p>>3)

// round hs to tf32 + permute
__global__ __launch_bounds__(256) void round_perm_kernel(
    const float* __restrict__ src, float* __restrict__ dst, int n4, int Kdim)
{
    int idx = blockIdx.x * 256 + threadIdx.x;
    if (idx >= n4) return;
    int q4 = Kdim >> 2;
    int m = idx / q4;
    int q = idx - m * q4;
    int kb = q >> 3;
    int j  = q & 7;
    const float* s = src + (long)m * Kdim + kb * 32;
    float4 o;
    int p0 = 4 * j;
    o.x = f2tf32(s[((p0    ) & 7) * 4 + ((p0    ) >> 3)]);
    o.y = f2tf32(s[((p0 + 1) & 7) * 4 + ((p0 + 1) >> 3)]);
    o.z = f2tf32(s[((p0 + 2) & 7) * 4 + ((p0 + 2) >> 3)]);
    o.w = f2tf32(s[((p0 + 3) & 7) * 4 + ((p0 + 3) >> 3)]);
    *(float4*)(dst + (long)m * Kdim + kb * 32 + p0) = o;
}

// merged transpose + round + permute for all 4 weights (z selects matrix)
__global__ __launch_bounds__(256) void transpose_perm_all_kernel(
    const float* __restrict__ Wq, const float* __restrict__ Wk,
    const float* __restrict__ Wv, const float* __restrict__ Wo,
    float* __restrict__ WTq, float* __restrict__ WTk,
    float* __restrict__ WTv, float* __restrict__ WTo)
{
    const float* W; float* WT; int K, N;
    switch (blockIdx.z) {
        case 0: W = Wq; WT = WTq; K = DD; N = NQK; break;
        case 1: W = Wk; WT = WTk; K = DD; N = NQK; break;
        case 2: W = Wv; WT = WTv; K = DD; N = NV;  break;
        default:W = Wo; WT = WTo; K = NV; N = DD;  break;
    }
    const int n0 = blockIdx.x * 32;
    const int k0 = blockIdx.y * 32;
    if (n0 >= N || k0 >= K) return;

    __shared__ float t[32][33];
    const int tx = threadIdx.x;       // 0..31
    const int ty = threadIdx.y;       // 0..7
#pragma unroll
    for (int i = 0; i < 4; i++)
        t[ty + 8*i][tx] = W[(long)(k0 + ty + 8*i) * N + n0 + tx];
    __syncthreads();
    int p0 = 4 * ty;
    float4 o;
    o.x = f2tf32(t[((p0    ) & 7) * 4 + ((p0    ) >> 3)][tx]);
    o.y = f2tf32(t[((p0 + 1) & 7) * 4 + ((p0 + 1) >> 3)][tx]);
    o.z = f2tf32(t[((p0 + 2) & 7) * 4 + ((p0 + 2) >> 3)][tx]);
    o.w = f2tf32(t[((p0 + 3) & 7) * 4 + ((p0 + 3) >> 3)][tx]);
    *(float4*)(WT + (long)(n0 + tx) * K + k0 + p0) = o;
}

// ---------------- tf32 mma.sync GEMM v6: 2 CTAs/SM -------------------------
// Per CTA: BM=128, BN=128, 256 threads (8 warps: 4 M x 2 N), warp tile 32x64.
// 3-stage cp.async ring (96KB) -> 2 CTAs co-resident per SM.
#define V6_STAGE_FLOATS (2*128*32)            // 8192 floats = 32KB (A+B)
#define V6_SM_BYTES (3*V6_STAGE_FLOATS*4)     // 98304

template<bool SILU>
__device__ __forceinline__ void gemm_v6_body(
    const float* __restrict__ A, const float* __restrict__ BT,
    float* __restrict__ C, int N, int K, int bm, int bn, float* sm)
{
    const int tid  = threadIdx.x;
    const int warp = tid >> 5;           // 0..7
    const int lane = tid & 31;
    const int g    = lane >> 2;          // 0..7
    const int tig  = lane & 3;           // 0..3
    const int wm   = (warp >> 1) * 32;   // 0,32,64,96
    const int wn   = (warp & 1) * 64;    // 0,64
    const int NIT  = K >> 5;

    float c[2][8][4];
#pragma unroll
    for (int mt = 0; mt < 2; mt++)
#pragma unroll
        for (int nt = 0; nt < 8; nt++)
#pragma unroll
            for (int r = 0; r < 4; r++) c[mt][nt][r] = 0.f;

    auto fill = [&](int t) {
        char* As = (char*)(sm + (t % 3) * V6_STAGE_FLOATS);
        char* Bs = As + 128 * 128;       // 16KB A
        const int kbase = t << 5;
        // A: 128 rows x 8 chunks = 1024, 4/thread
#pragma unroll
        for (int i = 0; i < 4; i++) {
            int idx = tid + i * 256;
            int row = idx >> 3;
            int j   = idx & 7;
            cp16(As + row * 128 + ((j ^ (row & 7)) << 4),
                 A + (long)(bm + row) * K + kbase + j * 4);
        }
        // B: 128 rows x 8 chunks = 1024, 4/thread
#pragma unroll
        for (int i = 0; i < 4; i++) {
            int idx = tid + i * 256;
            int row = idx >> 3;
            int j   = idx & 7;
            cp16(Bs + row * 128 + ((j ^ (row & 7)) << 4),
                 BT + (long)(bn + row) * K + kbase + j * 4);
        }
        asm volatile("cp.async.commit_group;");
    };

    fill(0); fill(1);

    for (int t = 0; t < NIT; t++) {
        if (t + 1 < NIT) asm volatile("cp.async.wait_group 1;");
        else             asm volatile("cp.async.wait_group 0;");
        __syncthreads();   // single barrier per iteration

        const char* Ab = (const char*)(sm + (t % 3) * V6_STAGE_FLOATS);
        const char* Bb = Ab + 128 * 128;

#pragma unroll
        for (int h = 0; h < 2; h++) {
            const int ch = ((2 * tig + h) ^ g) << 4;
            float4 av[2][2];
#pragma unroll
            for (int mt = 0; mt < 2; mt++) {
                int r1 = wm + mt * 16 + g;
                av[mt][0] = *(const float4*)(Ab + r1 * 128 + ch);
                av[mt][1] = *(const float4*)(Ab + (r1 + 8) * 128 + ch);
            }
#pragma unroll
            for (int ntp = 0; ntp < 4; ntp++) {
                float4 bv[2];
#pragma unroll
                for (int u = 0; u < 2; u++) {
                    int rn = wn + (ntp * 2 + u) * 8 + g;
                    bv[u] = *(const float4*)(Bb + rn * 128 + ch);
                }
#pragma unroll
                for (int u = 0; u < 2; u++) {
                    int nt = ntp * 2 + u;
#pragma unroll
                    for (int mt = 0; mt < 2; mt++) {
                        asm volatile(
                            "mma.sync.aligned.m16n8k8.row.col.f32.tf32.tf32.f32 "
                            "{%0,%1,%2,%3}, {%4,%5,%6,%7}, {%8,%9}, {%0,%1,%2,%3};"
                            : "+f"(c[mt][nt][0]), "+f"(c[mt][nt][1]),
                              "+f"(c[mt][nt][2]), "+f"(c[mt][nt][3])
                            : "r"(__float_as_uint(av[mt][0].x)), "r"(__float_as_uint(av[mt][1].x)),
                              "r"(__float_as_uint(av[mt][0].y)), "r"(__float_as_uint(av[mt][1].y)),
                              "r"(__float_as_uint(bv[u].x)), "r"(__float_as_uint(bv[u].y)));
                        asm volatile(
                            "mma.sync.aligned.m16n8k8.row.col.f32.tf32.tf32.f32 "
                            "{%0,%1,%2,%3}, {%4,%5,%6,%7}, {%8,%9}, {%0,%1,%2,%3};"
                            : "+f"(c[mt][nt][0]), "+f"(c[mt][nt][1]),
                              "+f"(c[mt][nt][2]), "+f"(c[mt][nt][3])
                            : "r"(__float_as_uint(av[mt][0].z)), "r"(__float_as_uint(av[mt][1].z)),
                              "r"(__float_as_uint(av[mt][0].w)), "r"(__float_as_uint(av[mt][1].w)),
                              "r"(__float_as_uint(bv[u].z)), "r"(__float_as_uint(bv[u].w)));
                    }
                }
            }
        }
        // Writes stage (t+2)%3 == (t-1)%3, whose readers passed the sync above.
        if (t + 2 < NIT) fill(t + 2);
    }

    // epilogue
#pragma unroll
    for (int mt = 0; mt < 2; mt++) {
        int r0 = bm + wm + mt * 16 + g;
#pragma unroll
        for (int nt = 0; nt < 8; nt++) {
            int col = bn + wn + nt * 8 + tig * 2;
            float x0 = c[mt][nt][0], x1 = c[mt][nt][1];
            float x2 = c[mt][nt][2], x3 = c[mt][nt][3];
            if (SILU) {
                x0 = x0 / (1.f + __expf(-x0));
                x1 = x1 / (1.f + __expf(-x1));
                x2 = x2 / (1.f + __expf(-x2));
                x3 = x3 / (1.f + __expf(-x3));
            }
            *(float2*)(C + (long)r0 * N + col)       = make_float2(x0, x1);
            *(float2*)(C + (long)(r0 + 8) * N + col) = make_float2(x2, x3);
        }
    }
}

// All three projections in one launch: grid (32, 32).
// x<8 -> q tile x; x<16 -> k tile x-8; else v tile x-16.
__global__ __launch_bounds__(256, 2) void tf32gemm_proj_kernel(
    const float* __restrict__ A,
    const float* __restrict__ BTq, const float* __restrict__ BTk,
    const float* __restrict__ BTv,
    float* __restrict__ Cq, float* __restrict__ Ck, float* __restrict__ Cv)
{
    extern __shared__ float sm[];
    const float* BT; float* C; int N; int bn;
    if (blockIdx.x < 8)       { BT = BTq; C = Cq; N = NQK; bn = blockIdx.x * 128; }
    else if (blockIdx.x < 16) { BT = BTk; C = Ck; N = NQK; bn = (blockIdx.x - 8) * 128; }
    else                      { BT = BTv; C = Cv; N = NV;  bn = (blockIdx.x - 16) * 128; }
    gemm_v6_body<true>(A, BT, C, N, DD, blockIdx.y * 128, bn, sm);
}

// Output projection (no activation): grid (16, 32).
__global__ __launch_bounds__(256, 2) void tf32gemm_out_kernel(
    const float* __restrict__ A, const float* __restrict__ BT,
    float* __restrict__ C)
{
    extern __shared__ float sm[];
    gemm_v6_body<false>(A, BT, C, DD, NV, blockIdx.y * 128, blockIdx.x * 128, sm);
}

// ---------------- fused low-rank stage 1: both gates, hs read once ----------
__global__ __launch_bounds__(256) void lowrank1_fused_kernel(
    const float* __restrict__ A, const float* __restrict__ W1,
    const float* __restrict__ W2, float* __restrict__ R1,
    float* __restrict__ R2, int K)
{
    const int warp = threadIdx.x >> 5;
    const int lane = threadIdx.x & 31;
    const int m = blockIdx.x * 8 + warp;
    const float* ap = A + (long)m * K;

    float acc1[16], acc2[16];
#pragma unroll
    for (int n = 0; n < 16; n++) { acc1[n] = 0.f; acc2[n] = 0.f; }

    for (int k = lane; k < K; k += 32) {
        float a = ap[k];
        const float4* w1 = (const float4*)(W1 + (long)k * 16);
        const float4* w2 = (const float4*)(W2 + (long)k * 16);
#pragma unroll
        for (int q = 0; q < 4; q++) {
            float4 u = w1[q];
            acc1[q*4+0] += a * u.x; acc1[q*4+1] += a * u.y;
            acc1[q*4+2] += a * u.z; acc1[q*4+3] += a * u.w;
            float4 v = w2[q];
            acc2[q*4+0] += a * v.x; acc2[q*4+1] += a * v.y;
            acc2[q*4+2] += a * v.z; acc2[q*4+3] += a * v.w;
        }
    }
#pragma unroll
    for (int n = 0; n < 16; n++) {
        float v = acc1[n];
        v += __shfl_xor_sync(0xffffffffu, v, 16);
        v += __shfl_xor_sync(0xffffffffu, v, 8);
        v += __shfl_xor_sync(0xffffffffu, v, 4);
        v += __shfl_xor_sync(0xffffffffu, v, 2);
        v += __shfl_xor_sync(0xffffffffu, v, 1);
        if (lane == 0) R1[(long)m * 16 + n] = v;
        float w = acc2[n];
        w += __shfl_xor_sync(0xffffffffu, w, 16);
        w += __shfl_xor_sync(0xffffffffu, w, 8);
        w += __shfl_xor_sync(0xffffffffu, w, 4);
        w += __shfl_xor_sync(0xffffffffu, w, 2);
        w += __shfl_xor_sync(0xffffffffu, w, 1);
        if (lane == 0) R2[(long)m * 16 + n] = w;
    }
}

// ---------------- low-rank stage 2 v2: 4 outputs/thread ----------------
__global__ __launch_bounds__(256) void lowrank2_kernel(
    const float* __restrict__ Rt, const float* __restrict__ W2,
    const float* __restrict__ bias, float* __restrict__ Out,
    int NOUT, int mode)
{
    int idx = blockIdx.x * 256 + threadIdx.x;   // over M*NOUT/4
    int q4 = NOUT >> 2;
    int m = idx / q4;
    int n = (idx - m * q4) << 2;
    const float* r = Rt + (long)m * 16;
    float4 acc = *(const float4*)&bias[n];
#pragma unroll
    for (int j = 0; j < 16; j++) {
        float rv = r[j];
        float4 w = *(const float4*)&W2[(long)j * NOUT + n];
        acc.x += rv * w.x; acc.y += rv * w.y;
        acc.z += rv * w.z; acc.w += rv * w.w;
    }
    if (mode) {
        float x;
        x = acc.x; acc.x = ((x >= 0.f) ? -log1pf(__expf(-x)) : (x - log1pf(__expf(x)))) * GLN_INV;
        x = acc.y; acc.y = ((x >= 0.f) ? -log1pf(__expf(-x)) : (x - log1pf(__expf(x)))) * GLN_INV;
        x = acc.z; acc.z = ((x >= 0.f) ? -log1pf(__expf(-x)) : (x - log1pf(__expf(x)))) * GLN_INV;
        x = acc.w; acc.w = ((x >= 0.f) ? -log1pf(__expf(-x)) : (x - log1pf(__expf(x)))) * GLN_INV;
    }
    *(float4*)&Out[(long)idx * 4] = acc;
}

// ---------------- GLA chunked recurrence (512 threads) ----------------
#define OFF_Q  0
#define OFF_K  4160
#define OFF_A  8320
#define OFF_V  12480
#define OFF_S  14592
#define OFF_GL 16704
#define SM_FLOATS 16768
#define SM_BYTES  (SM_FLOATS * 4)

__global__ __launch_bounds__(512) void gla_kernel(
    const float* __restrict__ Q, const float* __restrict__ Kx,
    const float* __restrict__ V, const float* __restrict__ GK,
    float* __restrict__ O)
{
    extern __shared__ float sm[];
    float* sq  = sm + OFF_Q;
    float* sk  = sm + OFF_K;
    float* sA  = sm + OFF_A;
    float* sv  = sm + OFF_V;
    float* sS  = sm + OFF_S;
    float* sGl = sm + OFF_GL;

    const int tid = threadIdx.x;
    const int s  = blockIdx.x & 3;
    const int bh = blockIdx.x >> 2;
    const int h  = bh & 15;
    const int b  = bh >> 4;
    const int e0 = s * 32;

    const int cb = tid & 63;
    const int eg = tid >> 6;

    for (int i = tid; i < 64 * 33; i += 512) sS[i] = 0.f;

    for (int ch = 0; ch < NCC; ch++) {
        __syncthreads();
        const long base = ((long)(b * TT + ch * 64) * HH + h);
        const float* qp  = Q  + base * DKq;
        const float* kp  = Kx + base * DKq;
        const float* gp  = GK + base * DKq;
        const float* vp  = V  + base * DVv + e0;

#pragma unroll
        for (int w = 0; w < 2; w++) {
            int f = w * 512 + tid;
            int c = f >> 4;
            int dq = (f & 15) << 2;
            float4 a4 = *(const float4*)(qp + (long)c * 1024 + dq);
            sq[c*65+dq]=a4.x; sq[c*65+dq+1]=a4.y; sq[c*65+dq+2]=a4.z; sq[c*65+dq+3]=a4.w;
            float4 b4 = *(const float4*)(kp + (long)c * 1024 + dq);
            sk[c*65+dq]=b4.x; sk[c*65+dq+1]=b4.y; sk[c*65+dq+2]=b4.z; sk[c*65+dq+3]=b4.w;
            float4 g4 = *(const float4*)(gp + (long)c * 1024 + dq);
            sA[c*65+dq]=g4.x; sA[c*65+dq+1]=g4.y; sA[c*65+dq+2]=g4.z; sA[c*65+dq+3]=g4.w;
        }
        {
            int f = tid;
            int c = f >> 3;
            int eq = (f & 7) << 2;
            float4 v4 = *(const float4*)(vp + (long)c * 2048 + eq);
            sv[c*33+eq]=v4.x; sv[c*33+eq+1]=v4.y; sv[c*33+eq+2]=v4.z; sv[c*33+eq+3]=v4.w;
        }
        __syncthreads();

        if (tid < 64) {
            int d = tid;
            float acc = 0.f;
            for (int c = 0; c < 64; c++) {
                acc += sA[c*65 + d];
                sA[c*65 + d] = acc;
            }
            sGl[d] = acc;
        }
        __syncthreads();

#pragma unroll
        for (int w = 0; w < 8; w++) {
            int f = w * 512 + tid;
            int c = f >> 6;
            int d = f & 63;
            float G = sA[c*65 + d];
            sq[c*65 + d] *= __expf(G) * 0.125f;
            sk[c*65 + d] *= __expf(-G);
        }
        if (tid < 64) sGl[tid] = __expf(sGl[tid]);
        __syncthreads();

        float o_r[4];
#pragma unroll
        for (int j = 0; j < 4; j++) o_r[j] = 0.f;
        {
            const int c = cb;
#pragma unroll 4
            for (int d = 0; d < 64; d++) {
                float qv = sq[c*65 + d];
                const float* Srow = &sS[d*33 + eg*4];
#pragma unroll
                for (int j = 0; j < 4; j++) o_r[j] += qv * Srow[j];
            }
        }
        {
            const int c = cb;
            const int jbase = eg * 8;
            float a[8];
#pragma unroll
            for (int jj = 0; jj < 8; jj++) a[jj] = 0.f;
#pragma unroll 2
            for (int d = 0; d < 64; d++) {
                float qv = sq[c*65 + d];
#pragma unroll
                for (int jj = 0; jj < 8; jj++)
                    a[jj] += qv * sk[(jbase + jj)*65 + d];
            }
#pragma unroll
            for (int jj = 0; jj < 8; jj++)
                sA[c*65 + jbase + jj] = (jbase + jj <= c) ? a[jj] : 0.f;
        }
        __syncthreads();

        {
            const int c = cb;
            for (int j64 = 0; j64 <= c; j64++) {
                float a = sA[c*65 + j64];
                const float* vr = &sv[j64*33 + eg*4];
#pragma unroll
                for (int j = 0; j < 4; j++) o_r[j] += a * vr[j];
            }
            float* op = O + (base + (long)c * HH) * DVv + e0 + eg * 4;
            *(float4*)(op) = make_float4(o_r[0], o_r[1], o_r[2], o_r[3]);
        }
        {
            const int d = cb;
            float* Srow = &sS[d*33 + eg*4];
            float acc[4];
#pragma unroll
            for (int j = 0; j < 4; j++) acc[j] = Srow[j];
#pragma unroll 4
            for (int c64 = 0; c64 < 64; c64++) {
                float kv = sk[c64*65 + d];
                const float* vr = &sv[c64*33 + eg*4];
#pragma unroll
                for (int j = 0; j < 4; j++) acc[j] += kv * vr[j];
            }
            float eGl = sGl[d];
#pragma unroll
            for (int j = 0; j < 4; j++) Srow[j] = acc[j] * eGl;
        }
    }
}

// ---------------- RMS norm + sigmoid gate, in-place tf32 + permuted ----------
__global__ __launch_bounds__(256) void rmsgate_kernel(
    float* __restrict__ O, const float* __restrict__ G,
    const float* __restrict__ gw)
{
    int row = blockIdx.x * 8 + (threadIdx.x >> 5);   // (b*T+t)*16 + h
    int lane = threadIdx.x & 31;
    long basei = (long)row * 128 + lane * 4;
    float4 o4 = *(float4*)&O[basei];
    float ss = o4.x*o4.x + o4.y*o4.y + o4.z*o4.z + o4.w*o4.w;
    ss += __shfl_xor_sync(0xffffffffu, ss, 16);
    ss += __shfl_xor_sync(0xffffffffu, ss, 8);
    ss += __shfl_xor_sync(0xffffffffu, ss, 4);
    ss += __shfl_xor_sync(0xffffffffu, ss, 2);
    ss += __shfl_xor_sync(0xffffffffu, ss, 1);
    float rr = rsqrtf(ss * (1.f / 128.f) + EPSL);
    float4 g4 = *(const float4*)&G[basei];
    float4 w4 = *(const float4*)&gw[lane * 4];
    float r0 = f2tf32(o4.x * rr * w4.x / (1.f + __expf(-g4.x)));
    float r1 = f2tf32(o4.y * rr * w4.y / (1.f + __expf(-g4.y)));
    float r2 = f2tf32(o4.z * rr * w4.z / (1.f + __expf(-g4.z)));
    float r3 = f2tf32(o4.w * rr * w4.w / (1.f + __expf(-g4.w)));
    long obase = (long)(row >> 4) * 2048 + ((row & 15) * 4 + (lane >> 3)) * 32 + (lane & 7);
    O[obase + 0 ] = r0;
    O[obase + 8 ] = r1;
    O[obase + 16] = r2;
    O[obase + 24] = r3;
}

// ---------------- launch ----------------
extern "C" void kernel_launch(void* const* d_in, const int* in_sizes, int n_in,
                              void* d_out, int out_size)
{
    const float* hs    = (const float*)d_in[0];
    const float* Wq    = (const float*)d_in[1];
    const float* Wk    = (const float*)d_in[2];
    const float* Wv    = (const float*)d_in[3];
    const float* Wgk1  = (const float*)d_in[4];
    const float* Wgk2  = (const float*)d_in[5];
    const float* bgk2  = (const float*)d_in[6];
    const float* Wg1   = (const float*)d_in[7];
    const float* Wg2   = (const float*)d_in[8];
    const float* bg2   = (const float*)d_in[9];
    const float* Wo    = (const float*)d_in[10];
    const float* gnw   = (const float*)d_in[11];
    float* out = (float*)d_out;

    float *pq, *pk, *pv, *pgk, *pr1, *pr2, *pg, *po;
    float *phsr, *pwqr, *pwkr, *pwvr, *pwor;
    cudaGetSymbolAddress((void**)&pq,  g_q);
    cudaGetSymbolAddress((void**)&pk,  g_k);
    cudaGetSymbolAddress((void**)&pv,  g_v);
    cudaGetSymbolAddress((void**)&pgk, g_gk);
    cudaGetSymbolAddress((void**)&pr1, g_r1);
    cudaGetSymbolAddress((void**)&pr2, g_r2);
    cudaGetSymbolAddress((void**)&pg,  g_g);
    cudaGetSymbolAddress((void**)&po,  g_o);
    cudaGetSymbolAddress((void**)&phsr, g_hsr);
    cudaGetSymbolAddress((void**)&pwqr, g_wqr);
    cudaGetSymbolAddress((void**)&pwkr, g_wkr);
    cudaGetSymbolAddress((void**)&pwvr, g_wvr);
    cudaGetSymbolAddress((void**)&pwor, g_wor);

    cudaFuncSetAttribute(tf32gemm_proj_kernel, cudaFuncAttributeMaxDynamicSharedMemorySize, V6_SM_BYTES);
    cudaFuncSetAttribute(tf32gemm_out_kernel,  cudaFuncAttributeMaxDynamicSharedMemorySize, V6_SM_BYTES);
    cudaFuncSetAttribute(gla_kernel, cudaFuncAttributeMaxDynamicSharedMemorySize, SM_BYTES);

    // 0: round+permute hs
    round_perm_kernel<<<(MM*DD/4 + 255)/256, 256>>>(hs, phsr, MM*DD/4, DD);
    // 1: all weight transposes
    {
        dim3 blk(32, 8);
        transpose_perm_all_kernel<<<dim3(64, 64, 4), blk>>>(
            Wq, Wk, Wv, Wo, pwqr, pwkr, pwvr, pwor);
    }
    // 2: fused low-rank stage 1
    lowrank1_fused_kernel<<<MM / 8, 256>>>(hs, Wgk1, Wg1, pr1, pr2, DD);
    // 3 (ncu-captured): all projections (q, k, v) — 1024 CTAs, 2/SM
    tf32gemm_proj_kernel<<<dim3(32, 32), 256, V6_SM_BYTES>>>(
        phsr, pwqr, pwkr, pwvr, pq, pk, pv);
    // 4: gk gate
    lowrank2_kernel<<<(MM * NQK / 4) / 256, 256>>>(pr1, Wgk2, bgk2, pgk, NQK, 1);
    // 5: output gate
    lowrank2_kernel<<<(MM * NV / 4) / 256, 256>>>(pr2, Wg2, bg2, pg, NV, 0);
    // 6: chunked GLA
    gla_kernel<<<BB * HH * 4, 512, SM_BYTES>>>(pq, pk, pv, pgk, po);
    // 7: rms norm + gate (writes permuted tf32 layout)
    rmsgate_kernel<<<(MM * HH) / 8, 256>>>(po, pg, gnw);
    // 8: output projection — 512 CTAs, 2/SM
    tf32gemm_out_kernel<<<dim3(16, 32), 256, V6_SM_BYTES>>>(po, pwor, out);
    (void)in_sizes; (void)n_in; (void)out_size;
}

// round 14
// speedup vs baseline: 1.7716x; 1.0280x over previous
#include <cuda_runtime.h>
#include <cuda_bf16.h>
#include <math.h>
#include <stdint.h>

// Problem constants
#define BB 2
#define TT 2048
#define DD 2048
#define HH 16
#define DKq 64
#define DVv 128
#define RR 16
#define CC 64
#define NCC 32
#define MM (BB*TT)          // 4096
#define NQK (HH*DKq)        // 1024
#define NV  (HH*DVv)        // 2048
#define GLN_INV (1.0f/16.0f)
#define EPSL 1e-5f

// ---------------- scratch (device globals, no allocs allowed) ----------------
__device__ float g_q [MM*NQK];
__device__ float g_k [MM*NQK];
__device__ float g_v [MM*NV];
__device__ float g_gk[MM*NQK];
__device__ float g_r1[MM*RR];
__device__ float g_r2[MM*RR];
__device__ float g_g [MM*NV];
__device__ float g_o [MM*NV];
__device__ float g_hsr[MM*DD];     // tf32-rounded + permuted hs
__device__ float g_wqr[DD*NQK];    // transposed [N][K] + permuted + rounded
__device__ float g_wkr[DD*NQK];
__device__ float g_wvr[DD*NV];
__device__ float g_wor[NV*DD];

// ---------------- helpers ----------------
__device__ __forceinline__ float f2tf32(float x) {
    uint32_t r;
    asm("cvt.rna.tf32.f32 %0, %1;" : "=r"(r) : "f"(x));
    return __uint_as_float(r);
}

__device__ __forceinline__ void cp16(void* smem_dst, const void* gmem_src) {
    uint32_t s = (uint32_t)__cvta_generic_to_shared(smem_dst);
    asm volatile("cp.async.cg.shared.global [%0], [%1], 16;" :: "r"(s), "l"(gmem_src));
}

// permutation within each 32-float K block: p(c) = (c&3)*8 + (c>>2)
// inverse: c(p) = (p&7)*4 + (p>>3)

// round hs to tf32 + permute
__global__ __launch_bounds__(256) void round_perm_kernel(
    const float* __restrict__ src, float* __restrict__ dst, int n4, int Kdim)
{
    int idx = blockIdx.x * 256 + threadIdx.x;
    if (idx >= n4) return;
    int q4 = Kdim >> 2;
    int m = idx / q4;
    int q = idx - m * q4;
    int kb = q >> 3;
    int j  = q & 7;
    const float* s = src + (long)m * Kdim + kb * 32;
    float4 o;
    int p0 = 4 * j;
    o.x = f2tf32(s[((p0    ) & 7) * 4 + ((p0    ) >> 3)]);
    o.y = f2tf32(s[((p0 + 1) & 7) * 4 + ((p0 + 1) >> 3)]);
    o.z = f2tf32(s[((p0 + 2) & 7) * 4 + ((p0 + 2) >> 3)]);
    o.w = f2tf32(s[((p0 + 3) & 7) * 4 + ((p0 + 3) >> 3)]);
    *(float4*)(dst + (long)m * Kdim + kb * 32 + p0) = o;
}

// merged transpose + round + permute for all 4 weights (z selects matrix)
__global__ __launch_bounds__(256) void transpose_perm_all_kernel(
    const float* __restrict__ Wq, const float* __restrict__ Wk,
    const float* __restrict__ Wv, const float* __restrict__ Wo,
    float* __restrict__ WTq, float* __restrict__ WTk,
    float* __restrict__ WTv, float* __restrict__ WTo)
{
    const float* W; float* WT; int K, N;
    switch (blockIdx.z) {
        case 0: W = Wq; WT = WTq; K = DD; N = NQK; break;
        case 1: W = Wk; WT = WTk; K = DD; N = NQK; break;
        case 2: W = Wv; WT = WTv; K = DD; N = NV;  break;
        default:W = Wo; WT = WTo; K = NV; N = DD;  break;
    }
    const int n0 = blockIdx.x * 32;
    const int k0 = blockIdx.y * 32;
    if (n0 >= N || k0 >= K) return;

    __shared__ float t[32][33];
    const int tx = threadIdx.x;       // 0..31
    const int ty = threadIdx.y;       // 0..7
#pragma unroll
    for (int i = 0; i < 4; i++)
        t[ty + 8*i][tx] = W[(long)(k0 + ty + 8*i) * N + n0 + tx];
    __syncthreads();
    int p0 = 4 * ty;
    float4 o;
    o.x = f2tf32(t[((p0    ) & 7) * 4 + ((p0    ) >> 3)][tx]);
    o.y = f2tf32(t[((p0 + 1) & 7) * 4 + ((p0 + 1) >> 3)][tx]);
    o.z = f2tf32(t[((p0 + 2) & 7) * 4 + ((p0 + 2) >> 3)][tx]);
    o.w = f2tf32(t[((p0 + 3) & 7) * 4 + ((p0 + 3) >> 3)][tx]);
    *(float4*)(WT + (long)(n0 + tx) * K + k0 + p0) = o;
}

// ---------------- tf32 mma.sync GEMM v6: 2 CTAs/SM (unchanged from R13) -----
#define V6_STAGE_FLOATS (2*128*32)            // 8192 floats = 32KB (A+B)
#define V6_SM_BYTES (3*V6_STAGE_FLOATS*4)     // 98304

template<bool SILU>
__device__ __forceinline__ void gemm_v6_body(
    const float* __restrict__ A, const float* __restrict__ BT,
    float* __restrict__ C, int N, int K, int bm, int bn, float* sm)
{
    const int tid  = threadIdx.x;
    const int warp = tid >> 5;           // 0..7
    const int lane = tid & 31;
    const int g    = lane >> 2;          // 0..7
    const int tig  = lane & 3;           // 0..3
    const int wm   = (warp >> 1) * 32;   // 0,32,64,96
    const int wn   = (warp & 1) * 64;    // 0,64
    const int NIT  = K >> 5;

    float c[2][8][4];
#pragma unroll
    for (int mt = 0; mt < 2; mt++)
#pragma unroll
        for (int nt = 0; nt < 8; nt++)
#pragma unroll
            for (int r = 0; r < 4; r++) c[mt][nt][r] = 0.f;

    auto fill = [&](int t) {
        char* As = (char*)(sm + (t % 3) * V6_STAGE_FLOATS);
        char* Bs = As + 128 * 128;
        const int kbase = t << 5;
#pragma unroll
        for (int i = 0; i < 4; i++) {
            int idx = tid + i * 256;
            int row = idx >> 3;
            int j   = idx & 7;
            cp16(As + row * 128 + ((j ^ (row & 7)) << 4),
                 A + (long)(bm + row) * K + kbase + j * 4);
        }
#pragma unroll
        for (int i = 0; i < 4; i++) {
            int idx = tid + i * 256;
            int row = idx >> 3;
            int j   = idx & 7;
            cp16(Bs + row * 128 + ((j ^ (row & 7)) << 4),
                 BT + (long)(bn + row) * K + kbase + j * 4);
        }
        asm volatile("cp.async.commit_group;");
    };

    fill(0); fill(1);

    for (int t = 0; t < NIT; t++) {
        if (t + 1 < NIT) asm volatile("cp.async.wait_group 1;");
        else             asm volatile("cp.async.wait_group 0;");
        __syncthreads();

        const char* Ab = (const char*)(sm + (t % 3) * V6_STAGE_FLOATS);
        const char* Bb = Ab + 128 * 128;

#pragma unroll
        for (int h = 0; h < 2; h++) {
            const int ch = ((2 * tig + h) ^ g) << 4;
            float4 av[2][2];
#pragma unroll
            for (int mt = 0; mt < 2; mt++) {
                int r1 = wm + mt * 16 + g;
                av[mt][0] = *(const float4*)(Ab + r1 * 128 + ch);
                av[mt][1] = *(const float4*)(Ab + (r1 + 8) * 128 + ch);
            }
#pragma unroll
            for (int ntp = 0; ntp < 4; ntp++) {
                float4 bv[2];
#pragma unroll
                for (int u = 0; u < 2; u++) {
                    int rn = wn + (ntp * 2 + u) * 8 + g;
                    bv[u] = *(const float4*)(Bb + rn * 128 + ch);
                }
#pragma unroll
                for (int u = 0; u < 2; u++) {
                    int nt = ntp * 2 + u;
#pragma unroll
                    for (int mt = 0; mt < 2; mt++) {
                        asm volatile(
                            "mma.sync.aligned.m16n8k8.row.col.f32.tf32.tf32.f32 "
                            "{%0,%1,%2,%3}, {%4,%5,%6,%7}, {%8,%9}, {%0,%1,%2,%3};"
                            : "+f"(c[mt][nt][0]), "+f"(c[mt][nt][1]),
                              "+f"(c[mt][nt][2]), "+f"(c[mt][nt][3])
                            : "r"(__float_as_uint(av[mt][0].x)), "r"(__float_as_uint(av[mt][1].x)),
                              "r"(__float_as_uint(av[mt][0].y)), "r"(__float_as_uint(av[mt][1].y)),
                              "r"(__float_as_uint(bv[u].x)), "r"(__float_as_uint(bv[u].y)));
                        asm volatile(
                            "mma.sync.aligned.m16n8k8.row.col.f32.tf32.tf32.f32 "
                            "{%0,%1,%2,%3}, {%4,%5,%6,%7}, {%8,%9}, {%0,%1,%2,%3};"
                            : "+f"(c[mt][nt][0]), "+f"(c[mt][nt][1]),
                              "+f"(c[mt][nt][2]), "+f"(c[mt][nt][3])
                            : "r"(__float_as_uint(av[mt][0].z)), "r"(__float_as_uint(av[mt][1].z)),
                              "r"(__float_as_uint(av[mt][0].w)), "r"(__float_as_uint(av[mt][1].w)),
                              "r"(__float_as_uint(bv[u].z)), "r"(__float_as_uint(bv[u].w)));
                    }
                }
            }
        }
        if (t + 2 < NIT) fill(t + 2);
    }

#pragma unroll
    for (int mt = 0; mt < 2; mt++) {
        int r0 = bm + wm + mt * 16 + g;
#pragma unroll
        for (int nt = 0; nt < 8; nt++) {
            int col = bn + wn + nt * 8 + tig * 2;
            float x0 = c[mt][nt][0], x1 = c[mt][nt][1];
            float x2 = c[mt][nt][2], x3 = c[mt][nt][3];
            if (SILU) {
                x0 = x0 / (1.f + __expf(-x0));
                x1 = x1 / (1.f + __expf(-x1));
                x2 = x2 / (1.f + __expf(-x2));
                x3 = x3 / (1.f + __expf(-x3));
            }
            *(float2*)(C + (long)r0 * N + col)       = make_float2(x0, x1);
            *(float2*)(C + (long)(r0 + 8) * N + col) = make_float2(x2, x3);
        }
    }
}

__global__ __launch_bounds__(256, 2) void tf32gemm_proj_kernel(
    const float* __restrict__ A,
    const float* __restrict__ BTq, const float* __restrict__ BTk,
    const float* __restrict__ BTv,
    float* __restrict__ Cq, float* __restrict__ Ck, float* __restrict__ Cv)
{
    extern __shared__ float sm[];
    const float* BT; float* C; int N; int bn;
    if (blockIdx.x < 8)       { BT = BTq; C = Cq; N = NQK; bn = blockIdx.x * 128; }
    else if (blockIdx.x < 16) { BT = BTk; C = Ck; N = NQK; bn = (blockIdx.x - 8) * 128; }
    else                      { BT = BTv; C = Cv; N = NV;  bn = (blockIdx.x - 16) * 128; }
    gemm_v6_body<true>(A, BT, C, N, DD, blockIdx.y * 128, bn, sm);
}

__global__ __launch_bounds__(256, 2) void tf32gemm_out_kernel(
    const float* __restrict__ A, const float* __restrict__ BT,
    float* __restrict__ C)
{
    extern __shared__ float sm[];
    gemm_v6_body<false>(A, BT, C, DD, NV, blockIdx.y * 128, blockIdx.x * 128, sm);
}

// ---------------- fused low-rank stage 1 ----------------
__global__ __launch_bounds__(256) void lowrank1_fused_kernel(
    const float* __restrict__ A, const float* __restrict__ W1,
    const float* __restrict__ W2, float* __restrict__ R1,
    float* __restrict__ R2, int K)
{
    const int warp = threadIdx.x >> 5;
    const int lane = threadIdx.x & 31;
    const int m = blockIdx.x * 8 + warp;
    const float* ap = A + (long)m * K;

    float acc1[16], acc2[16];
#pragma unroll
    for (int n = 0; n < 16; n++) { acc1[n] = 0.f; acc2[n] = 0.f; }

    for (int k = lane; k < K; k += 32) {
        float a = ap[k];
        const float4* w1 = (const float4*)(W1 + (long)k * 16);
        const float4* w2 = (const float4*)(W2 + (long)k * 16);
#pragma unroll
        for (int q = 0; q < 4; q++) {
            float4 u = w1[q];
            acc1[q*4+0] += a * u.x; acc1[q*4+1] += a * u.y;
            acc1[q*4+2] += a * u.z; acc1[q*4+3] += a * u.w;
            float4 v = w2[q];
            acc2[q*4+0] += a * v.x; acc2[q*4+1] += a * v.y;
            acc2[q*4+2] += a * v.z; acc2[q*4+3] += a * v.w;
        }
    }
#pragma unroll
    for (int n = 0; n < 16; n++) {
        float v = acc1[n];
        v += __shfl_xor_sync(0xffffffffu, v, 16);
        v += __shfl_xor_sync(0xffffffffu, v, 8);
        v += __shfl_xor_sync(0xffffffffu, v, 4);
        v += __shfl_xor_sync(0xffffffffu, v, 2);
        v += __shfl_xor_sync(0xffffffffu, v, 1);
        if (lane == 0) R1[(long)m * 16 + n] = v;
        float w = acc2[n];
        w += __shfl_xor_sync(0xffffffffu, w, 16);
        w += __shfl_xor_sync(0xffffffffu, w, 8);
        w += __shfl_xor_sync(0xffffffffu, w, 4);
        w += __shfl_xor_sync(0xffffffffu, w, 2);
        w += __shfl_xor_sync(0xffffffffu, w, 1);
        if (lane == 0) R2[(long)m * 16 + n] = w;
    }
}

// ---------------- low-rank stage 2 v2: 4 outputs/thread ----------------
__global__ __launch_bounds__(256) void lowrank2_kernel(
    const float* __restrict__ Rt, const float* __restrict__ W2,
    const float* __restrict__ bias, float* __restrict__ Out,
    int NOUT, int mode)
{
    int idx = blockIdx.x * 256 + threadIdx.x;   // over M*NOUT/4
    int q4 = NOUT >> 2;
    int m = idx / q4;
    int n = (idx - m * q4) << 2;
    const float* r = Rt + (long)m * 16;
    float4 acc = *(const float4*)&bias[n];
#pragma unroll
    for (int j = 0; j < 16; j++) {
        float rv = r[j];
        float4 w = *(const float4*)&W2[(long)j * NOUT + n];
        acc.x += rv * w.x; acc.y += rv * w.y;
        acc.z += rv * w.z; acc.w += rv * w.w;
    }
    if (mode) {
        float x;
        x = acc.x; acc.x = ((x >= 0.f) ? -log1pf(__expf(-x)) : (x - log1pf(__expf(x)))) * GLN_INV;
        x = acc.y; acc.y = ((x >= 0.f) ? -log1pf(__expf(-x)) : (x - log1pf(__expf(x)))) * GLN_INV;
        x = acc.z; acc.z = ((x >= 0.f) ? -log1pf(__expf(-x)) : (x - log1pf(__expf(x)))) * GLN_INV;
        x = acc.w; acc.w = ((x >= 0.f) ? -log1pf(__expf(-x)) : (x - log1pf(__expf(x)))) * GLN_INV;
    }
    *(float4*)&Out[(long)idx * 4] = acc;
}

// ---------------- GLA v2: prefetch + warp-scan cumsum + vectorized A ---------
// 512 threads, 128 blocks (b,h,s). smem (floats):
// sq[64*65], sk[64*64], sG[64*65] (G, then A), sv[64*33], sS[64*33], sGl[64]
#define OFF_Q  0
#define OFF_K  4160
#define OFF_G  8256
#define OFF_V  12416
#define OFF_S  14528
#define OFF_GL 16640
#define SM_FLOATS 16704
#define SM_BYTES  (SM_FLOATS * 4)

__global__ __launch_bounds__(512) void gla_kernel(
    const float* __restrict__ Q, const float* __restrict__ Kx,
    const float* __restrict__ V, const float* __restrict__ GK,
    float* __restrict__ O)
{
    extern __shared__ float sm[];
    float* sq  = sm + OFF_Q;
    float* sk  = sm + OFF_K;
    float* sG  = sm + OFF_G;
    float* sv  = sm + OFF_V;
    float* sS  = sm + OFF_S;
    float* sGl = sm + OFF_GL;

    const int tid  = threadIdx.x;
    const int warp = tid >> 5;
    const int lane = tid & 31;
    const int s  = blockIdx.x & 3;
    const int bh = blockIdx.x >> 2;
    const int h  = bh & 15;
    const int b  = bh >> 4;
    const int e0 = s * 32;

    const int cb = tid & 63;    // c (or d) role
    const int eg = tid >> 6;    // 0..7

    // load mapping (2 float4 per q/k/g, 1 per v)
    const int c0  = tid >> 4;            // 0..31
    const int dq0 = (tid & 15) << 2;
    const int c1  = c0 + 32;             // rows 32..63
    const int vc  = tid >> 3;            // 0..63
    const int veq = (tid & 7) << 2;

    for (int i = tid; i < 64 * 33; i += 512) sS[i] = 0.f;

    float4 pq0, pq1, pk0, pk1, pg0, pg1, pv4;
    auto prefetch = [&](int ch) {
        const long base = ((long)(b * TT + ch * 64) * HH + h);
        const float* qp = Q  + base * DKq;
        const float* kp = Kx + base * DKq;
        const float* gp = GK + base * DKq;
        const float* vp = V  + base * DVv + e0;
        pq0 = *(const float4*)(qp + (long)c0 * 1024 + dq0);
        pq1 = *(const float4*)(qp + (long)c1 * 1024 + dq0);
        pk0 = *(const float4*)(kp + (long)c0 * 1024 + dq0);
        pk1 = *(const float4*)(kp + (long)c1 * 1024 + dq0);
        pg0 = *(const float4*)(gp + (long)c0 * 1024 + dq0);
        pg1 = *(const float4*)(gp + (long)c1 * 1024 + dq0);
        pv4 = *(const float4*)(vp + (long)vc * 2048 + veq);
    };

    prefetch(0);

    for (int ch = 0; ch < NCC; ch++) {
        __syncthreads();   // previous chunk's consumers done
        // store prefetched tiles
        sq[c0*65+dq0]=pq0.x; sq[c0*65+dq0+1]=pq0.y; sq[c0*65+dq0+2]=pq0.z; sq[c0*65+dq0+3]=pq0.w;
        sq[c1*65+dq0]=pq1.x; sq[c1*65+dq0+1]=pq1.y; sq[c1*65+dq0+2]=pq1.z; sq[c1*65+dq0+3]=pq1.w;
        *(float4*)&sk[c0*64+dq0] = pk0;
        *(float4*)&sk[c1*64+dq0] = pk1;
        sG[c0*65+dq0]=pg0.x; sG[c0*65+dq0+1]=pg0.y; sG[c0*65+dq0+2]=pg0.z; sG[c0*65+dq0+3]=pg0.w;
        sG[c1*65+dq0]=pg1.x; sG[c1*65+dq0+1]=pg1.y; sG[c1*65+dq0+2]=pg1.z; sG[c1*65+dq0+3]=pg1.w;
        sv[vc*33+veq]=pv4.x; sv[vc*33+veq+1]=pv4.y; sv[vc*33+veq+2]=pv4.z; sv[vc*33+veq+3]=pv4.w;
        if (ch + 1 < NCC) prefetch(ch + 1);   // LDG hidden behind this chunk's compute
        __syncthreads();   // tiles ready

        // parallel cumsum: warp w scans columns d = w + rep*16
#pragma unroll
        for (int rep = 0; rep < 4; rep++) {
            int d = warp + rep * 16;
            float x0 = sG[lane * 65 + d];
            float x1 = sG[(lane + 32) * 65 + d];
#pragma unroll
            for (int off = 1; off < 32; off <<= 1) {
                float t = __shfl_up_sync(0xffffffffu, x0, off);
                if (lane >= off) x0 += t;
            }
            float tot0 = __shfl_sync(0xffffffffu, x0, 31);
#pragma unroll
            for (int off = 1; off < 32; off <<= 1) {
                float t = __shfl_up_sync(0xffffffffu, x1, off);
                if (lane >= off) x1 += t;
            }
            x1 += tot0;
            sG[lane * 65 + d] = x0;
            sG[(lane + 32) * 65 + d] = x1;
            if (lane == 31) sGl[d] = __expf(x1);
        }
        __syncthreads();

        // transform: qg = q*exp(G)/8 ; kg = k*exp(-G)
#pragma unroll
        for (int w = 0; w < 8; w++) {
            int f = w * 512 + tid;
            int c = f >> 6;
            int d = f & 63;
            float G = sG[c*65 + d];
            sq[c*65 + d] *= __expf(G) * 0.125f;
            sk[c*64 + d] *= __expf(-G);
        }
        __syncthreads();

        // o_inter = qg @ S
        float o_r[4];
#pragma unroll
        for (int j = 0; j < 4; j++) o_r[j] = 0.f;
        {
            const int c = cb;
#pragma unroll 4
            for (int d = 0; d < 64; d++) {
                float qv = sq[c*65 + d];
                const float* Srow = &sS[d*33 + eg*4];
#pragma unroll
                for (int j = 0; j < 4; j++) o_r[j] += qv * Srow[j];
            }
        }
        // A = qg @ kg^T (vectorized: sk row float4 broadcast)
        {
            const int c = cb;
            const int jbase = eg * 8;
            float a[8];
#pragma unroll
            for (int jj = 0; jj < 8; jj++) a[jj] = 0.f;
#pragma unroll 2
            for (int d0 = 0; d0 < 64; d0 += 4) {
                float q0 = sq[c*65 + d0];
                float q1 = sq[c*65 + d0 + 1];
                float q2 = sq[c*65 + d0 + 2];
                float q3 = sq[c*65 + d0 + 3];
#pragma unroll
                for (int jj = 0; jj < 8; jj++) {
                    float4 k4 = *(const float4*)&sk[(jbase + jj)*64 + d0];
                    a[jj] += q0 * k4.x + q1 * k4.y + q2 * k4.z + q3 * k4.w;
                }
            }
#pragma unroll
            for (int jj = 0; jj < 8; jj++)
                sG[c*65 + jbase + jj] = (jbase + jj <= c) ? a[jj] : 0.f;
        }
        __syncthreads();

        // o_intra = A @ v ; write o
        {
            const int c = cb;
            for (int j64 = 0; j64 <= c; j64++) {
                float a = sG[c*65 + j64];
                const float* vr = &sv[j64*33 + eg*4];
#pragma unroll
                for (int j = 0; j < 4; j++) o_r[j] += a * vr[j];
            }
            const long base = ((long)(b * TT + ch * 64) * HH + h);
            float* op = O + (base + (long)c * HH) * DVv + e0 + eg * 4;
            *(float4*)(op) = make_float4(o_r[0], o_r[1], o_r[2], o_r[3]);
        }
        // S update
        {
            const int d = cb;
            float* Srow = &sS[d*33 + eg*4];
            float acc[4];
#pragma unroll
            for (int j = 0; j < 4; j++) acc[j] = Srow[j];
#pragma unroll 4
            for (int c64 = 0; c64 < 64; c64++) {
                float kv = sk[c64*64 + d];
                const float* vr = &sv[c64*33 + eg*4];
#pragma unroll
                for (int j = 0; j < 4; j++) acc[j] += kv * vr[j];
            }
            float eGl = sGl[d];
#pragma unroll
            for (int j = 0; j < 4; j++) Srow[j] = acc[j] * eGl;
        }
    }
}

// ---------------- RMS norm + sigmoid gate, in-place tf32 + permuted ----------
__global__ __launch_bounds__(256) void rmsgate_kernel(
    float* __restrict__ O, const float* __restrict__ G,
    const float* __restrict__ gw)
{
    int row = blockIdx.x * 8 + (threadIdx.x >> 5);   // (b*T+t)*16 + h
    int lane = threadIdx.x & 31;
    long basei = (long)row * 128 + lane * 4;
    float4 o4 = *(float4*)&O[basei];
    float ss = o4.x*o4.x + o4.y*o4.y + o4.z*o4.z + o4.w*o4.w;
    ss += __shfl_xor_sync(0xffffffffu, ss, 16);
    ss += __shfl_xor_sync(0xffffffffu, ss, 8);
    ss += __shfl_xor_sync(0xffffffffu, ss, 4);
    ss += __shfl_xor_sync(0xffffffffu, ss, 2);
    ss += __shfl_xor_sync(0xffffffffu, ss, 1);
    float rr = rsqrtf(ss * (1.f / 128.f) + EPSL);
    float4 g4 = *(const float4*)&G[basei];
    float4 w4 = *(const float4*)&gw[lane * 4];
    float r0 = f2tf32(o4.x * rr * w4.x / (1.f + __expf(-g4.x)));
    float r1 = f2tf32(o4.y * rr * w4.y / (1.f + __expf(-g4.y)));
    float r2 = f2tf32(o4.z * rr * w4.z / (1.f + __expf(-g4.z)));
    float r3 = f2tf32(o4.w * rr * w4.w / (1.f + __expf(-g4.w)));
    long obase = (long)(row >> 4) * 2048 + ((row & 15) * 4 + (lane >> 3)) * 32 + (lane & 7);
    O[obase + 0 ] = r0;
    O[obase + 8 ] = r1;
    O[obase + 16] = r2;
    O[obase + 24] = r3;
}

// ---------------- launch ----------------
extern "C" void kernel_launch(void* const* d_in, const int* in_sizes, int n_in,
                              void* d_out, int out_size)
{
    const float* hs    = (const float*)d_in[0];
    const float* Wq    = (const float*)d_in[1];
    const float* Wk    = (const float*)d_in[2];
    const float* Wv    = (const float*)d_in[3];
    const float* Wgk1  = (const float*)d_in[4];
    const float* Wgk2  = (const float*)d_in[5];
    const float* bgk2  = (const float*)d_in[6];
    const float* Wg1   = (const float*)d_in[7];
    const float* Wg2   = (const float*)d_in[8];
    const float* bg2   = (const float*)d_in[9];
    const float* Wo    = (const float*)d_in[10];
    const float* gnw   = (const float*)d_in[11];
    float* out = (float*)d_out;

    float *pq, *pk, *pv, *pgk, *pr1, *pr2, *pg, *po;
    float *phsr, *pwqr, *pwkr, *pwvr, *pwor;
    cudaGetSymbolAddress((void**)&pq,  g_q);
    cudaGetSymbolAddress((void**)&pk,  g_k);
    cudaGetSymbolAddress((void**)&pv,  g_v);
    cudaGetSymbolAddress((void**)&pgk, g_gk);
    cudaGetSymbolAddress((void**)&pr1, g_r1);
    cudaGetSymbolAddress((void**)&pr2, g_r2);
    cudaGetSymbolAddress((void**)&pg,  g_g);
    cudaGetSymbolAddress((void**)&po,  g_o);
    cudaGetSymbolAddress((void**)&phsr, g_hsr);
    cudaGetSymbolAddress((void**)&pwqr, g_wqr);
    cudaGetSymbolAddress((void**)&pwkr, g_wkr);
    cudaGetSymbolAddress((void**)&pwvr, g_wvr);
    cudaGetSymbolAddress((void**)&pwor, g_wor);

    cudaFuncSetAttribute(tf32gemm_proj_kernel, cudaFuncAttributeMaxDynamicSharedMemorySize, V6_SM_BYTES);
    cudaFuncSetAttribute(tf32gemm_out_kernel,  cudaFuncAttributeMaxDynamicSharedMemorySize, V6_SM_BYTES);
    cudaFuncSetAttribute(gla_kernel, cudaFuncAttributeMaxDynamicSharedMemorySize, SM_BYTES);

    // 0: round+permute hs
    round_perm_kernel<<<(MM*DD/4 + 255)/256, 256>>>(hs, phsr, MM*DD/4, DD);
    // 1: all weight transposes
    {
        dim3 blk(32, 8);
        transpose_perm_all_kernel<<<dim3(64, 64, 4), blk>>>(
            Wq, Wk, Wv, Wo, pwqr, pwkr, pwvr, pwor);
    }
    // 2: fused low-rank stage 1
    lowrank1_fused_kernel<<<MM / 8, 256>>>(hs, Wgk1, Wg1, pr1, pr2, DD);
    // 3 (ncu-captured): all projections (q, k, v) — 1024 CTAs, 2/SM
    tf32gemm_proj_kernel<<<dim3(32, 32), 256, V6_SM_BYTES>>>(
        phsr, pwqr, pwkr, pwvr, pq, pk, pv);
    // 4: gk gate
    lowrank2_kernel<<<(MM * NQK / 4) / 256, 256>>>(pr1, Wgk2, bgk2, pgk, NQK, 1);
    // 5: output gate
    lowrank2_kernel<<<(MM * NV / 4) / 256, 256>>>(pr2, Wg2, bg2, pg, NV, 0);
    // 6: chunked GLA v2
    gla_kernel<<<BB * HH * 4, 512, SM_BYTES>>>(pq, pk, pv, pgk, po);
    // 7: rms norm + gate (writes permuted tf32 layout)
    rmsgate_kernel<<<(MM * HH) / 8, 256>>>(po, pg, gnw);
    // 8: output projection — 512 CTAs, 2/SM
    tf32gemm_out_kernel<<<dim3(16, 32), 256, V6_SM_BYTES>>>(po, pwor, out);
    (void)in_sizes; (void)n_in; (void)out_size;
}

// round 17
// speedup vs baseline: 1.8397x; 1.0384x over previous
#include <cuda_runtime.h>
#include <cuda_bf16.h>
#include <math.h>
#include <stdint.h>

// Problem constants
#define BB 2
#define TT 2048
#define DD 2048
#define HH 16
#define DKq 64
#define DVv 128
#define RR 16
#define CC 64
#define NCC 32
#define MM (BB*TT)          // 4096
#define NQK (HH*DKq)        // 1024
#define NV  (HH*DVv)        // 2048
#define GLN_INV (1.0f/16.0f)
#define EPSL 1e-5f

// ---------------- scratch (device globals, no allocs allowed) ----------------
__device__ float g_q [MM*NQK];
__device__ float g_k [MM*NQK];
__device__ float g_v [MM*NV];
__device__ float g_gk[MM*NQK];
__device__ float g_gl[BB*HH*NCC*64];
__device__ float g_r1[MM*RR];
__device__ float g_r2[MM*RR];
__device__ float g_g [MM*NV];
__device__ float g_o [MM*NV];
__device__ float g_hsr[MM*DD];     // tf32-rounded + permuted hs
__device__ float g_wqr[DD*NQK];    // transposed [N][K] + permuted + rounded
__device__ float g_wkr[DD*NQK];
__device__ float g_wvr[DD*NV];
__device__ float g_wor[NV*DD];

// ---------------- helpers ----------------
__device__ __forceinline__ float f2tf32(float x) {
    uint32_t r;
    asm("cvt.rna.tf32.f32 %0, %1;" : "=r"(r) : "f"(x));
    return __uint_as_float(r);
}

__device__ __forceinline__ void cp16(void* smem_dst, const void* gmem_src) {
    uint32_t s = (uint32_t)__cvta_generic_to_shared(smem_dst);
    asm volatile("cp.async.cg.shared.global [%0], [%1], 16;" :: "r"(s), "l"(gmem_src));
}

// permutation within each 32-float K block: p(c) = (c&3)*8 + (c>>2)
// inverse: c(p) = (p&7)*4 + (p>>3)

// round hs to tf32 + permute
__global__ __launch_bounds__(256) void round_perm_kernel(
    const float* __restrict__ src, float* __restrict__ dst, int n4, int Kdim)
{
    int idx = blockIdx.x * 256 + threadIdx.x;
    if (idx >= n4) return;
    int q4 = Kdim >> 2;
    int m = idx / q4;
    int q = idx - m * q4;
    int kb = q >> 3;
    int j  = q & 7;
    const float* s = src + (long)m * Kdim + kb * 32;
    float4 o;
    int p0 = 4 * j;
    o.x = f2tf32(s[((p0    ) & 7) * 4 + ((p0    ) >> 3)]);
    o.y = f2tf32(s[((p0 + 1) & 7) * 4 + ((p0 + 1) >> 3)]);
    o.z = f2tf32(s[((p0 + 2) & 7) * 4 + ((p0 + 2) >> 3)]);
    o.w = f2tf32(s[((p0 + 3) & 7) * 4 + ((p0 + 3) >> 3)]);
    *(float4*)(dst + (long)m * Kdim + kb * 32 + p0) = o;
}

// merged transpose + round + permute for all 4 weights (z selects matrix)
__global__ __launch_bounds__(256) void transpose_perm_all_kernel(
    const float* __restrict__ Wq, const float* __restrict__ Wk,
    const float* __restrict__ Wv, const float* __restrict__ Wo,
    float* __restrict__ WTq, float* __restrict__ WTk,
    float* __restrict__ WTv, float* __restrict__ WTo)
{
    const float* W; float* WT; int K, N;
    switch (blockIdx.z) {
        case 0: W = Wq; WT = WTq; K = DD; N = NQK; break;
        case 1: W = Wk; WT = WTk; K = DD; N = NQK; break;
        case 2: W = Wv; WT = WTv; K = DD; N = NV;  break;
        default:W = Wo; WT = WTo; K = NV; N = DD;  break;
    }
    const int n0 = blockIdx.x * 32;
    const int k0 = blockIdx.y * 32;
    if (n0 >= N || k0 >= K) return;

    __shared__ float t[32][33];
    const int tx = threadIdx.x;       // 0..31
    const int ty = threadIdx.y;       // 0..7
#pragma unroll
    for (int i = 0; i < 4; i++)
        t[ty + 8*i][tx] = W[(long)(k0 + ty + 8*i) * N + n0 + tx];
    __syncthreads();
    int p0 = 4 * ty;
    float4 o;
    o.x = f2tf32(t[((p0    ) & 7) * 4 + ((p0    ) >> 3)][tx]);
    o.y = f2tf32(t[((p0 + 1) & 7) * 4 + ((p0 + 1) >> 3)][tx]);
    o.z = f2tf32(t[((p0 + 2) & 7) * 4 + ((p0 + 2) >> 3)][tx]);
    o.w = f2tf32(t[((p0 + 3) & 7) * 4 + ((p0 + 3) >> 3)][tx]);
    *(float4*)(WT + (long)(n0 + tx) * K + k0 + p0) = o;
}

// ---------------- tf32 mma.sync GEMM v6: 2 CTAs/SM (unchanged from R13) -----
#define V6_STAGE_FLOATS (2*128*32)            // 8192 floats = 32KB (A+B)
#define V6_SM_BYTES (3*V6_STAGE_FLOATS*4)     // 98304

template<bool SILU>
__device__ __forceinline__ void gemm_v6_body(
    const float* __restrict__ A, const float* __restrict__ BT,
    float* __restrict__ C, int N, int K, int bm, int bn, float* sm)
{
    const int tid  = threadIdx.x;
    const int warp = tid >> 5;           // 0..7
    const int lane = tid & 31;
    const int g    = lane >> 2;          // 0..7
    const int tig  = lane & 3;           // 0..3
    const int wm   = (warp >> 1) * 32;   // 0,32,64,96
    const int wn   = (warp & 1) * 64;    // 0,64
    const int NIT  = K >> 5;

    float c[2][8][4];
#pragma unroll
    for (int mt = 0; mt < 2; mt++)
#pragma unroll
        for (int nt = 0; nt < 8; nt++)
#pragma unroll
            for (int r = 0; r < 4; r++) c[mt][nt][r] = 0.f;

    auto fill = [&](int t) {
        char* As = (char*)(sm + (t % 3) * V6_STAGE_FLOATS);
        char* Bs = As + 128 * 128;
        const int kbase = t << 5;
#pragma unroll
        for (int i = 0; i < 4; i++) {
            int idx = tid + i * 256;
            int row = idx >> 3;
            int j   = idx & 7;
            cp16(As + row * 128 + ((j ^ (row & 7)) << 4),
                 A + (long)(bm + row) * K + kbase + j * 4);
        }
#pragma unroll
        for (int i = 0; i < 4; i++) {
            int idx = tid + i * 256;
            int row = idx >> 3;
            int j   = idx & 7;
            cp16(Bs + row * 128 + ((j ^ (row & 7)) << 4),
                 BT + (long)(bn + row) * K + kbase + j * 4);
        }
        asm volatile("cp.async.commit_group;");
    };

    fill(0); fill(1);

    for (int t = 0; t < NIT; t++) {
        if (t + 1 < NIT) asm volatile("cp.async.wait_group 1;");
        else             asm volatile("cp.async.wait_group 0;");
        __syncthreads();

        const char* Ab = (const char*)(sm + (t % 3) * V6_STAGE_FLOATS);
        const char* Bb = Ab + 128 * 128;

#pragma unroll
        for (int h = 0; h < 2; h++) {
            const int ch = ((2 * tig + h) ^ g) << 4;
            float4 av[2][2];
#pragma unroll
            for (int mt = 0; mt < 2; mt++) {
                int r1 = wm + mt * 16 + g;
                av[mt][0] = *(const float4*)(Ab + r1 * 128 + ch);
                av[mt][1] = *(const float4*)(Ab + (r1 + 8) * 128 + ch);
            }
#pragma unroll
            for (int ntp = 0; ntp < 4; ntp++) {
                float4 bv[2];
#pragma unroll
                for (int u = 0; u < 2; u++) {
                    int rn = wn + (ntp * 2 + u) * 8 + g;
                    bv[u] = *(const float4*)(Bb + rn * 128 + ch);
                }
#pragma unroll
                for (int u = 0; u < 2; u++) {
                    int nt = ntp * 2 + u;
#pragma unroll
                    for (int mt = 0; mt < 2; mt++) {
                        asm volatile(
                            "mma.sync.aligned.m16n8k8.row.col.f32.tf32.tf32.f32 "
                            "{%0,%1,%2,%3}, {%4,%5,%6,%7}, {%8,%9}, {%0,%1,%2,%3};"
                            : "+f"(c[mt][nt][0]), "+f"(c[mt][nt][1]),
                              "+f"(c[mt][nt][2]), "+f"(c[mt][nt][3])
                            : "r"(__float_as_uint(av[mt][0].x)), "r"(__float_as_uint(av[mt][1].x)),
                              "r"(__float_as_uint(av[mt][0].y)), "r"(__float_as_uint(av[mt][1].y)),
                              "r"(__float_as_uint(bv[u].x)), "r"(__float_as_uint(bv[u].y)));
                        asm volatile(
                            "mma.sync.aligned.m16n8k8.row.col.f32.tf32.tf32.f32 "
                            "{%0,%1,%2,%3}, {%4,%5,%6,%7}, {%8,%9}, {%0,%1,%2,%3};"
                            : "+f"(c[mt][nt][0]), "+f"(c[mt][nt][1]),
                              "+f"(c[mt][nt][2]), "+f"(c[mt][nt][3])
                            : "r"(__float_as_uint(av[mt][0].z)), "r"(__float_as_uint(av[mt][1].z)),
                              "r"(__float_as_uint(av[mt][0].w)), "r"(__float_as_uint(av[mt][1].w)),
                              "r"(__float_as_uint(bv[u].z)), "r"(__float_as_uint(bv[u].w)));
                    }
                }
            }
        }
        if (t + 2 < NIT) fill(t + 2);
    }

#pragma unroll
    for (int mt = 0; mt < 2; mt++) {
        int r0 = bm + wm + mt * 16 + g;
#pragma unroll
        for (int nt = 0; nt < 8; nt++) {
            int col = bn + wn + nt * 8 + tig * 2;
            float x0 = c[mt][nt][0], x1 = c[mt][nt][1];
            float x2 = c[mt][nt][2], x3 = c[mt][nt][3];
            if (SILU) {
                x0 = x0 / (1.f + __expf(-x0));
                x1 = x1 / (1.f + __expf(-x1));
                x2 = x2 / (1.f + __expf(-x2));
                x3 = x3 / (1.f + __expf(-x3));
            }
            *(float2*)(C + (long)r0 * N + col)       = make_float2(x0, x1);
            *(float2*)(C + (long)(r0 + 8) * N + col) = make_float2(x2, x3);
        }
    }
}

__global__ __launch_bounds__(256, 2) void tf32gemm_proj_kernel(
    const float* __restrict__ A,
    const float* __restrict__ BTq, const float* __restrict__ BTk,
    const float* __restrict__ BTv,
    float* __restrict__ Cq, float* __restrict__ Ck, float* __restrict__ Cv)
{
    extern __shared__ float sm[];
    const float* BT; float* C; int N; int bn;
    if (blockIdx.x < 8)       { BT = BTq; C = Cq; N = NQK; bn = blockIdx.x * 128; }
    else if (blockIdx.x < 16) { BT = BTk; C = Ck; N = NQK; bn = (blockIdx.x - 8) * 128; }
    else                      { BT = BTv; C = Cv; N = NV;  bn = (blockIdx.x - 16) * 128; }
    gemm_v6_body<true>(A, BT, C, N, DD, blockIdx.y * 128, bn, sm);
}

__global__ __launch_bounds__(256, 2) void tf32gemm_out_kernel(
    const float* __restrict__ A, const float* __restrict__ BT,
    float* __restrict__ C)
{
    extern __shared__ float sm[];
    gemm_v6_body<false>(A, BT, C, DD, NV, blockIdx.y * 128, blockIdx.x * 128, sm);
}

// ---------------- fused low-rank stage 1 ----------------
__global__ __launch_bounds__(256) void lowrank1_fused_kernel(
    const float* __restrict__ A, const float* __restrict__ W1,
    const float* __restrict__ W2, float* __restrict__ R1,
    float* __restrict__ R2, int K)
{
    const int warp = threadIdx.x >> 5;
    const int lane = threadIdx.x & 31;
    const int m = blockIdx.x * 8 + warp;
    const float* ap = A + (long)m * K;

    float acc1[16], acc2[16];
#pragma unroll
    for (int n = 0; n < 16; n++) { acc1[n] = 0.f; acc2[n] = 0.f; }

    for (int k = lane; k < K; k += 32) {
        float a = ap[k];
        const float4* w1 = (const float4*)(W1 + (long)k * 16);
        const float4* w2 = (const float4*)(W2 + (long)k * 16);
#pragma unroll
        for (int q = 0; q < 4; q++) {
            float4 u = w1[q];
            acc1[q*4+0] += a * u.x; acc1[q*4+1] += a * u.y;
            acc1[q*4+2] += a * u.z; acc1[q*4+3] += a * u.w;
            float4 v = w2[q];
            acc2[q*4+0] += a * v.x; acc2[q*4+1] += a * v.y;
            acc2[q*4+2] += a * v.z; acc2[q*4+3] += a * v.w;
        }
    }
#pragma unroll
    for (int n = 0; n < 16; n++) {
        float v = acc1[n];
        v += __shfl_xor_sync(0xffffffffu, v, 16);
        v += __shfl_xor_sync(0xffffffffu, v, 8);
        v += __shfl_xor_sync(0xffffffffu, v, 4);
        v += __shfl_xor_sync(0xffffffffu, v, 2);
        v += __shfl_xor_sync(0xffffffffu, v, 1);
        if (lane == 0) R1[(long)m * 16 + n] = v;
        float w = acc2[n];
        w += __shfl_xor_sync(0xffffffffu, w, 16);
        w += __shfl_xor_sync(0xffffffffu, w, 8);
        w += __shfl_xor_sync(0xffffffffu, w, 4);
        w += __shfl_xor_sync(0xffffffffu, w, 2);
        w += __shfl_xor_sync(0xffffffffu, w, 1);
        if (lane == 0) R2[(long)m * 16 + n] = w;
    }
}

// ---------------- low-rank stage 2 v2: 4 outputs/thread ----------------
__global__ __launch_bounds__(256) void lowrank2_kernel(
    const float* __restrict__ Rt, const float* __restrict__ W2,
    const float* __restrict__ bias, float* __restrict__ Out,
    int NOUT, int mode)
{
    int idx = blockIdx.x * 256 + threadIdx.x;   // over M*NOUT/4
    int q4 = NOUT >> 2;
    int m = idx / q4;
    int n = (idx - m * q4) << 2;
    const float* r = Rt + (long)m * 16;
    float4 acc = *(const float4*)&bias[n];
#pragma unroll
    for (int j = 0; j < 16; j++) {
        float rv = r[j];
        float4 w = *(const float4*)&W2[(long)j * NOUT + n];
        acc.x += rv * w.x; acc.y += rv * w.y;
        acc.z += rv * w.z; acc.w += rv * w.w;
    }
    if (mode) {
        float x;
        x = acc.x; acc.x = ((x >= 0.f) ? -log1pf(__expf(-x)) : (x - log1pf(__expf(x)))) * GLN_INV;
        x = acc.y; acc.y = ((x >= 0.f) ? -log1pf(__expf(-x)) : (x - log1pf(__expf(x)))) * GLN_INV;
        x = acc.z; acc.z = ((x >= 0.f) ? -log1pf(__expf(-x)) : (x - log1pf(__expf(x)))) * GLN_INV;
        x = acc.w; acc.w = ((x >= 0.f) ? -log1pf(__expf(-x)) : (x - log1pf(__expf(x)))) * GLN_INV;
    }
    *(float4*)&Out[(long)idx * 4] = acc;
}

// ---------------- gk prepass: cumsum + exp transform, once per (b,h,ch) -----
// grid = BB*HH*NCC = 1024 blocks, 256 threads.
// In place: q <- q*exp(G)*DK^-0.5 ; k <- k*exp(-G). GL[bh][ch][d] = exp(G_last).
__global__ __launch_bounds__(256) void gk_prepass_kernel(
    float* __restrict__ Q, float* __restrict__ Kx,
    const float* __restrict__ GK, float* __restrict__ GL)
{
    __shared__ float sG[64 * 65];
    const int tid  = threadIdx.x;
    const int warp = tid >> 5;          // 0..7
    const int lane = tid & 31;
    const int ch = blockIdx.x & 31;
    const int bh = blockIdx.x >> 5;     // b*16+h
    const int h  = bh & 15;
    const int b  = bh >> 4;
    const long rbase = ((long)(b * TT + ch * 64) * HH + h) * DKq;  // row stride 1024

    // load gk tile: 4096 floats, 16/thread
#pragma unroll
    for (int i = 0; i < 4; i++) {
        int idx = tid + i * 256;
        int c = idx >> 4;
        int d = (idx & 15) << 2;
        float4 g4 = *(const float4*)(GK + rbase + (long)c * 1024 + d);
        sG[c*65+d]=g4.x; sG[c*65+d+1]=g4.y; sG[c*65+d+2]=g4.z; sG[c*65+d+3]=g4.w;
    }
    __syncthreads();

    // warp-scan cumsum: warp w scans columns d = warp + rep*8
#pragma unroll
    for (int rep = 0; rep < 8; rep++) {
        int d = warp + rep * 8;
        float x0 = sG[lane * 65 + d];
        float x1 = sG[(lane + 32) * 65 + d];
#pragma unroll
        for (int off = 1; off < 32; off <<= 1) {
            float t = __shfl_up_sync(0xffffffffu, x0, off);
            if (lane >= off) x0 += t;
        }
        float tot0 = __shfl_sync(0xffffffffu, x0, 31);
#pragma unroll
        for (int off = 1; off < 32; off <<= 1) {
            float t = __shfl_up_sync(0xffffffffu, x1, off);
            if (lane >= off) x1 += t;
        }
        x1 += tot0;
        sG[lane * 65 + d] = x0;
        sG[(lane + 32) * 65 + d] = x1;
        if (lane == 31) GL[((long)bh * NCC + ch) * 64 + d] = __expf(x1);
    }
    __syncthreads();

    // transform q, k in place
#pragma unroll
    for (int i = 0; i < 4; i++) {
        int idx = tid + i * 256;
        int c = idx >> 4;
        int d = (idx & 15) << 2;
        const long off = rbase + (long)c * 1024 + d;
        float4 q4 = *(const float4*)(Q + off);
        float4 k4 = *(const float4*)(Kx + off);
        float G0 = sG[c*65+d], G1 = sG[c*65+d+1], G2 = sG[c*65+d+2], G3 = sG[c*65+d+3];
        q4.x *= __expf(G0) * 0.125f; q4.y *= __expf(G1) * 0.125f;
        q4.z *= __expf(G2) * 0.125f; q4.w *= __expf(G3) * 0.125f;
        k4.x *= __expf(-G0); k4.y *= __expf(-G1);
        k4.z *= __expf(-G2); k4.w *= __expf(-G3);
        *(float4*)(Q + off)  = q4;
        *(float4*)(Kx + off) = k4;
    }
}

// ---------------- GLA v3: pure recurrence (pre-transformed q/k) --------------
// 512 threads, 128 blocks (b,h,s). smem (floats):
// sq[64*65], sk[64*64], sA[64*65], sv[64*33], sS[64*33], sGl[64]
#define OFF_Q  0
#define OFF_K  4160
#define OFF_A  8256
#define OFF_V  12416
#define OFF_S  14528
#define OFF_GL 16640
#define SM_FLOATS 16704
#define SM_BYTES  (SM_FLOATS * 4)

__global__ __launch_bounds__(512) void gla_kernel(
    const float* __restrict__ Q, const float* __restrict__ Kx,
    const float* __restrict__ V, const float* __restrict__ GL,
    float* __restrict__ O)
{
    extern __shared__ float sm[];
    float* sq  = sm + OFF_Q;
    float* sk  = sm + OFF_K;
    float* sA  = sm + OFF_A;
    float* sv  = sm + OFF_V;
    float* sS  = sm + OFF_S;
    float* sGl = sm + OFF_GL;

    const int tid  = threadIdx.x;
    const int s  = blockIdx.x & 3;
    const int bh = blockIdx.x >> 2;
    const int h  = bh & 15;
    const int b  = bh >> 4;
    const int e0 = s * 32;

    const int cb = tid & 63;    // c (or d) role
    const int eg = tid >> 6;    // 0..7

    const int c0  = tid >> 4;            // 0..31
    const int dq0 = (tid & 15) << 2;
    const int c1  = c0 + 32;
    const int vc  = tid >> 3;            // 0..63
    const int veq = (tid & 7) << 2;

    for (int i = tid; i < 64 * 33; i += 512) sS[i] = 0.f;

    float4 pq0, pq1, pk0, pk1, pv4;
    float pgl = 0.f;
    auto prefetch = [&](int ch) {
        const long base = ((long)(b * TT + ch * 64) * HH + h);
        const float* qp = Q  + base * DKq;
        const float* kp = Kx + base * DKq;
        const float* vp = V  + base * DVv + e0;
        pq0 = *(const float4*)(qp + (long)c0 * 1024 + dq0);
        pq1 = *(const float4*)(qp + (long)c1 * 1024 + dq0);
        pk0 = *(const float4*)(kp + (long)c0 * 1024 + dq0);
        pk1 = *(const float4*)(kp + (long)c1 * 1024 + dq0);
        pv4 = *(const float4*)(vp + (long)vc * 2048 + veq);
        if (tid < 64) pgl = GL[((long)bh * NCC + ch) * 64 + tid];
    };

    prefetch(0);

    for (int ch = 0; ch < NCC; ch++) {
        __syncthreads();   // previous chunk fully consumed
        sq[c0*65+dq0]=pq0.x; sq[c0*65+dq0+1]=pq0.y; sq[c0*65+dq0+2]=pq0.z; sq[c0*65+dq0+3]=pq0.w;
        sq[c1*65+dq0]=pq1.x; sq[c1*65+dq0+1]=pq1.y; sq[c1*65+dq0+2]=pq1.z; sq[c1*65+dq0+3]=pq1.w;
        *(float4*)&sk[c0*64+dq0] = pk0;
        *(float4*)&sk[c1*64+dq0] = pk1;
        sv[vc*33+veq]=pv4.x; sv[vc*33+veq+1]=pv4.y; sv[vc*33+veq+2]=pv4.z; sv[vc*33+veq+3]=pv4.w;
        if (tid < 64) sGl[tid] = pgl;
        if (ch + 1 < NCC) prefetch(ch + 1);
        __syncthreads();   // tiles ready

        // o_inter = qg @ S
        float o_r[4];
#pragma unroll
        for (int j = 0; j < 4; j++) o_r[j] = 0.f;
        {
            const int c = cb;
#pragma unroll 4
            for (int d = 0; d < 64; d++) {
                float qv = sq[c*65 + d];
                const float* Srow = &sS[d*33 + eg*4];
#pragma unroll
                for (int j = 0; j < 4; j++) o_r[j] += qv * Srow[j];
            }
        }
        // A = qg @ kg^T
        {
            const int c = cb;
            const int jbase = eg * 8;
            float a[8];
#pragma unroll
            for (int jj = 0; jj < 8; jj++) a[jj] = 0.f;
#pragma unroll 2
            for (int d0 = 0; d0 < 64; d0 += 4) {
                float q0 = sq[c*65 + d0];
                float q1 = sq[c*65 + d0 + 1];
                float q2 = sq[c*65 + d0 + 2];
                float q3 = sq[c*65 + d0 + 3];
#pragma unroll
                for (int jj = 0; jj < 8; jj++) {
                    float4 k4 = *(const float4*)&sk[(jbase + jj)*64 + d0];
                    a[jj] += q0 * k4.x + q1 * k4.y + q2 * k4.z + q3 * k4.w;
                }
            }
#pragma unroll
            for (int jj = 0; jj < 8; jj++)
                sA[c*65 + jbase + jj] = (jbase + jj <= c) ? a[jj] : 0.f;
        }
        __syncthreads();

        // o_intra = A @ v ; write o
        {
            const int c = cb;
            for (int j64 = 0; j64 <= c; j64++) {
                float a = sA[c*65 + j64];
                const float* vr = &sv[j64*33 + eg*4];
#pragma unroll
                for (int j = 0; j < 4; j++) o_r[j] += a * vr[j];
            }
            const long base = ((long)(b * TT + ch * 64) * HH + h);
            float* op = O + (base + (long)c * HH) * DVv + e0 + eg * 4;
            *(float4*)(op) = make_float4(o_r[0], o_r[1], o_r[2], o_r[3]);
        }
        // S update
        {
            const int d = cb;
            float* Srow = &sS[d*33 + eg*4];
            float acc[4];
#pragma unroll
            for (int j = 0; j < 4; j++) acc[j] = Srow[j];
#pragma unroll 4
            for (int c64 = 0; c64 < 64; c64++) {
                float kv = sk[c64*64 + d];
                const float* vr = &sv[c64*33 + eg*4];
#pragma unroll
                for (int j = 0; j < 4; j++) acc[j] += kv * vr[j];
            }
            float eGl = sGl[d];
#pragma unroll
            for (int j = 0; j < 4; j++) Srow[j] = acc[j] * eGl;
        }
    }
}

// ---------------- RMS norm + sigmoid gate, in-place tf32 + permuted ----------
__global__ __launch_bounds__(256) void rmsgate_kernel(
    float* __restrict__ O, const float* __restrict__ G,
    const float* __restrict__ gw)
{
    int row = blockIdx.x * 8 + (threadIdx.x >> 5);   // (b*T+t)*16 + h
    int lane = threadIdx.x & 31;
    long basei = (long)row * 128 + lane * 4;
    float4 o4 = *(float4*)&O[basei];
    float ss = o4.x*o4.x + o4.y*o4.y + o4.z*o4.z + o4.w*o4.w;
    ss += __shfl_xor_sync(0xffffffffu, ss, 16);
    ss += __shfl_xor_sync(0xffffffffu, ss, 8);
    ss += __shfl_xor_sync(0xffffffffu, ss, 4);
    ss += __shfl_xor_sync(0xffffffffu, ss, 2);
    ss += __shfl_xor_sync(0xffffffffu, ss, 1);
    float rr = rsqrtf(ss * (1.f / 128.f) + EPSL);
    float4 g4 = *(const float4*)&G[basei];
    float4 w4 = *(const float4*)&gw[lane * 4];
    float r0 = f2tf32(o4.x * rr * w4.x / (1.f + __expf(-g4.x)));
    float r1 = f2tf32(o4.y * rr * w4.y / (1.f + __expf(-g4.y)));
    float r2 = f2tf32(o4.z * rr * w4.z / (1.f + __expf(-g4.z)));
    float r3 = f2tf32(o4.w * rr * w4.w / (1.f + __expf(-g4.w)));
    long obase = (long)(row >> 4) * 2048 + ((row & 15) * 4 + (lane >> 3)) * 32 + (lane & 7);
    O[obase + 0 ] = r0;
    O[obase + 8 ] = r1;
    O[obase + 16] = r2;
    O[obase + 24] = r3;
}

// ---------------- launch ----------------
extern "C" void kernel_launch(void* const* d_in, const int* in_sizes, int n_in,
                              void* d_out, int out_size)
{
    const float* hs    = (const float*)d_in[0];
    const float* Wq    = (const float*)d_in[1];
    const float* Wk    = (const float*)d_in[2];
    const float* Wv    = (const float*)d_in[3];
    const float* Wgk1  = (const float*)d_in[4];
    const float* Wgk2  = (const float*)d_in[5];
    const float* bgk2  = (const float*)d_in[6];
    const float* Wg1   = (const float*)d_in[7];
    const float* Wg2   = (const float*)d_in[8];
    const float* bg2   = (const float*)d_in[9];
    const float* Wo    = (const float*)d_in[10];
    const float* gnw   = (const float*)d_in[11];
    float* out = (float*)d_out;

    float *pq, *pk, *pv, *pgk, *pgl, *pr1, *pr2, *pg, *po;
    float *phsr, *pwqr, *pwkr, *pwvr, *pwor;
    cudaGetSymbolAddress((void**)&pq,  g_q);
    cudaGetSymbolAddress((void**)&pk,  g_k);
    cudaGetSymbolAddress((void**)&pv,  g_v);
    cudaGetSymbolAddress((void**)&pgk, g_gk);
    cudaGetSymbolAddress((void**)&pgl, g_gl);
    cudaGetSymbolAddress((void**)&pr1, g_r1);
    cudaGetSymbolAddress((void**)&pr2, g_r2);
    cudaGetSymbolAddress((void**)&pg,  g_g);
    cudaGetSymbolAddress((void**)&po,  g_o);
    cudaGetSymbolAddress((void**)&phsr, g_hsr);
    cudaGetSymbolAddress((void**)&pwqr, g_wqr);
    cudaGetSymbolAddress((void**)&pwkr, g_wkr);
    cudaGetSymbolAddress((void**)&pwvr, g_wvr);
    cudaGetSymbolAddress((void**)&pwor, g_wor);

    cudaFuncSetAttribute(tf32gemm_proj_kernel, cudaFuncAttributeMaxDynamicSharedMemorySize, V6_SM_BYTES);
    cudaFuncSetAttribute(tf32gemm_out_kernel,  cudaFuncAttributeMaxDynamicSharedMemorySize, V6_SM_BYTES);
    cudaFuncSetAttribute(gla_kernel, cudaFuncAttributeMaxDynamicSharedMemorySize, SM_BYTES);

    // 0: round+permute hs
    round_perm_kernel<<<(MM*DD/4 + 255)/256, 256>>>(hs, phsr, MM*DD/4, DD);
    // 1: all weight transposes
    {
        dim3 blk(32, 8);
        transpose_perm_all_kernel<<<dim3(64, 64, 4), blk>>>(
            Wq, Wk, Wv, Wo, pwqr, pwkr, pwvr, pwor);
    }
    // 2: fused low-rank stage 1
    lowrank1_fused_kernel<<<MM / 8, 256>>>(hs, Wgk1, Wg1, pr1, pr2, DD);
    // 3 (ncu-captured): all projections (q, k, v) — 1024 CTAs, 2/SM
    tf32gemm_proj_kernel<<<dim3(32, 32), 256, V6_SM_BYTES>>>(
        phsr, pwqr, pwkr, pwvr, pq, pk, pv);
    // 4: gk gate
    lowrank2_kernel<<<(MM * NQK / 4) / 256, 256>>>(pr1, Wgk2, bgk2, pgk, NQK, 1);
    // 5: output gate
    lowrank2_kernel<<<(MM * NV / 4) / 256, 256>>>(pr2, Wg2, bg2, pg, NV, 0);
    // 6: gk prepass — cumsum + exp transform, fully parallel over (b,h,ch)
    gk_prepass_kernel<<<BB * HH * NCC, 256>>>(pq, pk, pgk, pgl);
    // 7: chunked GLA recurrence (no exp, no cumsum)
    gla_kernel<<<BB * HH * 4, 512, SM_BYTES>>>(pq, pk, pv, pgl, po);
    // 8: rms norm + gate (writes permuted tf32 layout)
    rmsgate_kernel<<<(MM * HH) / 8, 256>>>(po, pg, gnw);
    // 9: output projection — 512 CTAs, 2/SM
    tf32gemm_out_kernel<<<dim3(16, 32), 256, V6_SM_BYTES>>>(po, pwor, out);
    (void)in_sizes; (void)n_in; (void)out_size;
}